// round 1
// baseline (speedup 1.0000x reference)
#include <cuda_runtime.h>
#include <cuda_bf16.h>
#include <math.h>

// Problem shape (fixed by the reference): B=8, S=1024, H=1024, heads=16, d=64
#define B_    8
#define S_    1024
#define H_    1024
#define NH_   16
#define D_    64
#define M_TOT (B_ * S_)      // 8192 rows of X

// Scratch for Q/K/V in head-major layout [b*16+h][s][64]
__device__ float g_q[(size_t)M_TOT * H_];
__device__ float g_k[(size_t)M_TOT * H_];
__device__ float g_v[(size_t)M_TOT * H_];

// ---------------------------------------------------------------------------
// QKV GEMM: Y = X @ W^T + b, X [8192,1024], W [1024,1024] (row-major, K contig)
// 128x128 block tile, BK=16, 8x8 per-thread microtile, 256 threads.
// gridDim.z selects (qw,qb)->g_q, (kw,kb)->g_k, (vw,vb)->g_v.
// Epilogue scatters to head-major scratch.
// ---------------------------------------------------------------------------
#define BM 128
#define BN 128
#define BK 16
#define TM 8
#define TN 8

__global__ __launch_bounds__(256) void qkv_gemm(
    const float* __restrict__ X,
    const float* __restrict__ Wq, const float* __restrict__ bq,
    const float* __restrict__ Wk, const float* __restrict__ bk,
    const float* __restrict__ Wv, const float* __restrict__ bv)
{
    const float* W;
    const float* bias;
    float* out;
    if (blockIdx.z == 0)      { W = Wq; bias = bq; out = g_q; }
    else if (blockIdx.z == 1) { W = Wk; bias = bk; out = g_k; }
    else                      { W = Wv; bias = bv; out = g_v; }

    __shared__ float As[BK][BM + 4];
    __shared__ float Bs[BK][BN + 4];

    const int m0  = blockIdx.y * BM;
    const int n0  = blockIdx.x * BN;
    const int tid = threadIdx.x;
    const int tx  = tid & 15;
    const int ty  = tid >> 4;
    const int tm0 = ty * TM;
    const int tn0 = tx * TN;

    float acc[TM][TN];
    #pragma unroll
    for (int i = 0; i < TM; i++)
        #pragma unroll
        for (int j = 0; j < TN; j++) acc[i][j] = 0.f;

    for (int k0 = 0; k0 < H_; k0 += BK) {
        // 512 float4 per tile per matrix; 2 per thread.
        #pragma unroll
        for (int i = 0; i < 2; i++) {
            int f   = tid + i * 256;        // 0..511
            int row = f >> 2;               // 0..127
            int kq  = (f & 3) * 4;          // 0,4,8,12
            float4 a = *(const float4*)(X + (size_t)(m0 + row) * H_ + k0 + kq);
            As[kq + 0][row] = a.x; As[kq + 1][row] = a.y;
            As[kq + 2][row] = a.z; As[kq + 3][row] = a.w;
            float4 b = *(const float4*)(W + (size_t)(n0 + row) * H_ + k0 + kq);
            Bs[kq + 0][row] = b.x; Bs[kq + 1][row] = b.y;
            Bs[kq + 2][row] = b.z; Bs[kq + 3][row] = b.w;
        }
        __syncthreads();

        #pragma unroll
        for (int kk = 0; kk < BK; kk++) {
            float ra[TM], rb[TN];
            #pragma unroll
            for (int i = 0; i < TM; i++) ra[i] = As[kk][tm0 + i];
            #pragma unroll
            for (int j = 0; j < TN; j++) rb[j] = Bs[kk][tn0 + j];
            #pragma unroll
            for (int i = 0; i < TM; i++)
                #pragma unroll
                for (int j = 0; j < TN; j++)
                    acc[i][j] = fmaf(ra[i], rb[j], acc[i][j]);
        }
        __syncthreads();
    }

    // Epilogue: m = b*1024+s ; n = h*64+dd -> out[((b*16+h)*1024+s)*64+dd]
    #pragma unroll
    for (int i = 0; i < TM; i++) {
        int m = m0 + tm0 + i;
        int b = m >> 10;
        int s = m & 1023;
        #pragma unroll
        for (int j = 0; j < TN; j += 4) {
            int n  = n0 + tn0 + j;
            int h  = n >> 6;
            int dd = n & 63;
            float4 v;
            v.x = acc[i][j + 0] + bias[n + 0];
            v.y = acc[i][j + 1] + bias[n + 1];
            v.z = acc[i][j + 2] + bias[n + 2];
            v.w = acc[i][j + 3] + bias[n + 3];
            *(float4*)(out + (((size_t)(b * NH_ + h) * S_) + s) * D_ + dd) = v;
        }
    }
}

// ---------------------------------------------------------------------------
// Flash-style attention. One thread = one query row. 128 queries per block,
// 128 (b,h) pairs x 8 q-tiles = 1024 blocks. K/V tiled through smem (64 keys).
// Online softmax with branchy max-rescale (rare, amortized).
// ---------------------------------------------------------------------------
#define TKK 64

__global__ __launch_bounds__(128) void attn(
    const float* __restrict__ mask,  // [B][1024]
    float* __restrict__ out)         // [B][S][H]
{
    const int bh  = blockIdx.x;          // 0..127
    const int qt  = blockIdx.y;          // 0..7
    const int b   = bh >> 4;
    const int h   = bh & 15;
    const int tid = threadIdx.x;         // 0..127
    const int q   = qt * 128 + tid;

    __shared__ float ks[TKK][D_];
    __shared__ float vs[TKK][D_];
    __shared__ float ms[TKK];

    // Query row into registers (16 x float4 = 64 floats)
    const float* qptr = g_q + ((size_t)bh * S_ + q) * D_;
    float4 qreg[16];
    #pragma unroll
    for (int i = 0; i < 16; i++) qreg[i] = *(const float4*)(qptr + i * 4);

    float acc[D_];
    #pragma unroll
    for (int dd = 0; dd < D_; dd++) acc[dd] = 0.f;
    float mmax = -1e30f;
    float lsum = 0.f;
    const float scale = 0.125f;  // 1/sqrt(64)

    const float* kbase = g_k + (size_t)bh * S_ * D_;
    const float* vbase = g_v + (size_t)bh * S_ * D_;
    const float* mbase = mask + (size_t)b * S_;

    for (int k0 = 0; k0 < S_; k0 += TKK) {
        __syncthreads();
        // Load K/V tiles: 4096 floats each = 1024 float4; 8 per thread.
        #pragma unroll
        for (int i = 0; i < 8; i++) {
            int f   = tid + i * 128;     // 0..1023
            int row = f >> 4;
            int col = (f & 15) * 4;
            *(float4*)&ks[row][col] = *(const float4*)(kbase + (size_t)(k0 + row) * D_ + col);
            *(float4*)&vs[row][col] = *(const float4*)(vbase + (size_t)(k0 + row) * D_ + col);
        }
        if (tid < TKK) ms[tid] = mbase[k0 + tid];
        __syncthreads();

        #pragma unroll 4
        for (int tk = 0; tk < TKK; tk++) {
            const float4* kv = (const float4*)ks[tk];
            float s0 = 0.f, s1 = 0.f, s2 = 0.f, s3 = 0.f;
            #pragma unroll
            for (int i = 0; i < 16; i += 4) {
                float4 k0v = kv[i + 0], k1v = kv[i + 1], k2v = kv[i + 2], k3v = kv[i + 3];
                s0 = fmaf(qreg[i + 0].x, k0v.x, s0); s0 = fmaf(qreg[i + 0].y, k0v.y, s0);
                s0 = fmaf(qreg[i + 0].z, k0v.z, s0); s0 = fmaf(qreg[i + 0].w, k0v.w, s0);
                s1 = fmaf(qreg[i + 1].x, k1v.x, s1); s1 = fmaf(qreg[i + 1].y, k1v.y, s1);
                s1 = fmaf(qreg[i + 1].z, k1v.z, s1); s1 = fmaf(qreg[i + 1].w, k1v.w, s1);
                s2 = fmaf(qreg[i + 2].x, k2v.x, s2); s2 = fmaf(qreg[i + 2].y, k2v.y, s2);
                s2 = fmaf(qreg[i + 2].z, k2v.z, s2); s2 = fmaf(qreg[i + 2].w, k2v.w, s2);
                s3 = fmaf(qreg[i + 3].x, k3v.x, s3); s3 = fmaf(qreg[i + 3].y, k3v.y, s3);
                s3 = fmaf(qreg[i + 3].z, k3v.z, s3); s3 = fmaf(qreg[i + 3].w, k3v.w, s3);
            }
            float s = (s0 + s1) + (s2 + s3);
            s = fmaf(s, scale, ms[tk]);

            if (s > mmax) {                       // rare: rescale state
                float corr = __expf(mmax - s);
                lsum *= corr;
                #pragma unroll
                for (int dd = 0; dd < D_; dd++) acc[dd] *= corr;
                mmax = s;
            }
            float p = __expf(s - mmax);
            lsum += p;
            const float4* vv = (const float4*)vs[tk];
            #pragma unroll
            for (int i = 0; i < 16; i++) {
                float4 v4 = vv[i];
                acc[i * 4 + 0] = fmaf(p, v4.x, acc[i * 4 + 0]);
                acc[i * 4 + 1] = fmaf(p, v4.y, acc[i * 4 + 1]);
                acc[i * 4 + 2] = fmaf(p, v4.z, acc[i * 4 + 2]);
                acc[i * 4 + 3] = fmaf(p, v4.w, acc[i * 4 + 3]);
            }
        }
    }

    const float inv = 1.f / lsum;
    float* op = out + ((size_t)(b * S_ + q)) * H_ + h * D_;
    #pragma unroll
    for (int i = 0; i < 16; i++) {
        float4 v;
        v.x = acc[i * 4 + 0] * inv;
        v.y = acc[i * 4 + 1] * inv;
        v.z = acc[i * 4 + 2] * inv;
        v.w = acc[i * 4 + 3] * inv;
        *(float4*)(op + i * 4) = v;
    }
}

// ---------------------------------------------------------------------------
// Launch
// ---------------------------------------------------------------------------
extern "C" void kernel_launch(void* const* d_in, const int* in_sizes, int n_in,
                              void* d_out, int out_size)
{
    const float* act  = (const float*)d_in[0];   // [8,1,1024,1024]
    const float* mask = (const float*)d_in[1];   // [8,1,1,1024]
    const float* qw   = (const float*)d_in[2];
    const float* qb   = (const float*)d_in[3];
    const float* kw   = (const float*)d_in[4];
    const float* kb   = (const float*)d_in[5];
    const float* vw   = (const float*)d_in[6];
    const float* vb   = (const float*)d_in[7];
    float* out = (float*)d_out;

    dim3 g1(H_ / BN, M_TOT / BM, 3);   // 8 x 64 x 3
    qkv_gemm<<<g1, 256>>>(act, qw, qb, kw, kb, vw, vb);

    dim3 g2(B_ * NH_, S_ / 128);       // 128 x 8
    attn<<<g2, 128>>>(mask, out);
}

// round 4
// speedup vs baseline: 1.3745x; 1.3745x over previous
#include <cuda_runtime.h>
#include <cuda_bf16.h>
#include <math.h>
#include <stdint.h>

// Problem shape: B=8, S=1024, H=1024, heads=16, d=64
#define B_    8
#define S_    1024
#define H_    1024
#define NH_   16
#define D_    64
#define M_TOT (B_ * S_)      // 8192 rows of X

// ---------------------------------------------------------------------------
// Device scratch
// ---------------------------------------------------------------------------
__device__ float g_q[(size_t)M_TOT * H_];
__device__ float g_k[(size_t)M_TOT * H_];
__device__ float g_v[(size_t)M_TOT * H_];

__device__ __nv_bfloat16 g_xh[(size_t)M_TOT * H_];   // X hi
__device__ __nv_bfloat16 g_xl[(size_t)M_TOT * H_];   // X lo
__device__ __nv_bfloat16 g_wh[(size_t)3 * H_ * H_];  // [q|k|v] W hi
__device__ __nv_bfloat16 g_wl[(size_t)3 * H_ * H_];  // [q|k|v] W lo

#define XN_ ((size_t)M_TOT * H_)
#define WN_ ((size_t)H_ * H_)

// ---------------------------------------------------------------------------
// Helpers (sm_100 baseline ISA only: cp.async / ldmatrix / mma.sync)
// ---------------------------------------------------------------------------
__device__ __forceinline__ uint32_t smem_u32(const void* p) {
    uint32_t a;
    asm("{ .reg .u64 t; cvta.to.shared.u64 t, %1; cvt.u32.u64 %0, t; }"
        : "=r"(a) : "l"(p));
    return a;
}

__device__ __forceinline__ uint32_t swz(uint32_t off) {
    return off ^ ((off >> 3) & 0x70);
}

__device__ __forceinline__ void cp16(uint32_t dst, const void* src) {
    asm volatile("cp.async.cg.shared.global [%0], [%1], 16;"
                 :: "r"(dst), "l"(src) : "memory");
}
#define CP_COMMIT() asm volatile("cp.async.commit_group;" ::: "memory")
#define CP_WAIT0()  asm volatile("cp.async.wait_group 0;" ::: "memory")

__device__ __forceinline__ void ldsm4(uint32_t& r0, uint32_t& r1,
                                      uint32_t& r2, uint32_t& r3, uint32_t a) {
    asm volatile("ldmatrix.sync.aligned.m8n8.x4.shared.b16 {%0,%1,%2,%3}, [%4];"
                 : "=r"(r0), "=r"(r1), "=r"(r2), "=r"(r3) : "r"(a));
}

__device__ __forceinline__ void mma16816(float& c0, float& c1, float& c2, float& c3,
                                         uint32_t a0, uint32_t a1, uint32_t a2, uint32_t a3,
                                         uint32_t b0, uint32_t b1) {
    asm volatile(
        "mma.sync.aligned.m16n8k16.row.col.f32.bf16.bf16.f32 "
        "{%0,%1,%2,%3}, {%4,%5,%6,%7}, {%8,%9}, {%0,%1,%2,%3};"
        : "+f"(c0), "+f"(c1), "+f"(c2), "+f"(c3)
        : "r"(a0), "r"(a1), "r"(a2), "r"(a3), "r"(b0), "r"(b1));
}

// ---------------------------------------------------------------------------
// fp32 -> (bf16 hi, bf16 lo) split of X and the three weight matrices
// ---------------------------------------------------------------------------
__global__ __launch_bounds__(512) void convert_split(
    const float* __restrict__ X,
    const float* __restrict__ qw, const float* __restrict__ kw,
    const float* __restrict__ vw)
{
    size_t total = XN_ + 3 * WN_;
    for (size_t i = (size_t)blockIdx.x * blockDim.x + threadIdx.x;
         i < total; i += (size_t)gridDim.x * blockDim.x) {
        float x;
        __nv_bfloat16 *dh, *dl;
        if (i < XN_) {
            x = X[i]; dh = g_xh + i; dl = g_xl + i;
        } else {
            size_t j = i - XN_;
            size_t z = j / WN_;
            size_t r = j - z * WN_;
            x = (z == 0 ? qw : (z == 1 ? kw : vw))[r];
            dh = g_wh + j; dl = g_wl + j;
        }
        __nv_bfloat16 hi = __float2bfloat16_rn(x);
        __nv_bfloat16 lo = __float2bfloat16_rn(x - __bfloat162float(hi));
        *dh = hi; *dl = lo;
    }
}

// ---------------------------------------------------------------------------
// bf16x3 QKV GEMM via mma.sync: Y = X @ W^T + b -> head-major scratch.
// CTA 128x128, BK=64, 8 warps (2m x 4n), warp tile 64x32, 2-stage cp.async.
// grid: (8 n-tiles, 64 m-tiles, 3 matrices), 256 threads.
// ---------------------------------------------------------------------------
#define TILE_B   (128 * 128)                 // one [128 rows x 128B] tile, bytes
#define STG_SZ   (4 * TILE_B)                // Ah, Al, Bh, Bl per stage = 64 KB
#define GSMEM    (2 * STG_SZ)                // 128 KB

#define OFF_AH2(s) ((s) * STG_SZ)
#define OFF_AL2(s) ((s) * STG_SZ + TILE_B)
#define OFF_BH2(s) ((s) * STG_SZ + 2 * TILE_B)
#define OFF_BL2(s) ((s) * STG_SZ + 3 * TILE_B)

__global__ __launch_bounds__(256, 1) void qkv_mma(
    const float* __restrict__ bq, const float* __restrict__ bk,
    const float* __restrict__ bv)
{
    extern __shared__ char smem[];
    const uint32_t sb = smem_u32(smem);

    const int tid  = threadIdx.x;
    const int wid  = tid >> 5;
    const int lane = tid & 31;
    const int z    = blockIdx.z;
    const int m0   = blockIdx.y * 128;
    const int n0   = blockIdx.x * 128;

    const float* bias = (z == 0) ? bq : (z == 1) ? bk : bv;
    float* out        = (z == 0) ? g_q : (z == 1) ? g_k : g_v;

    const int warp_m = (wid >> 2) * 64;   // 0 or 64
    const int warp_n = (wid & 3) * 32;    // 0,32,64,96

    const __nv_bfloat16* Xh = g_xh + (size_t)m0 * H_;
    const __nv_bfloat16* Xl = g_xl + (size_t)m0 * H_;
    const __nv_bfloat16* Wh = g_wh + (size_t)z * WN_ + (size_t)n0 * H_;
    const __nv_bfloat16* Wl = g_wl + (size_t)z * WN_ + (size_t)n0 * H_;

    float acc[4][4][4];
    #pragma unroll
    for (int i = 0; i < 4; i++)
        #pragma unroll
        for (int j = 0; j < 4; j++)
            #pragma unroll
            for (int t = 0; t < 4; t++) acc[i][j][t] = 0.f;

    // Per-thread load coordinates: 1024 16B-chunks per tile, 4 per thread.
    const int lrow0 = tid >> 3;          // +32 per it
    const int lj    = (tid & 7) * 16;    // byte col in 128B row

    auto load_chunk = [&](int c, int s) {
        const int k0 = c * 64;
        const uint32_t sAh = sb + OFF_AH2(s), sAl = sb + OFF_AL2(s);
        const uint32_t sBh = sb + OFF_BH2(s), sBl = sb + OFF_BL2(s);
        #pragma unroll
        for (int it = 0; it < 4; it++) {
            const int row = lrow0 + it * 32;
            const uint32_t so = swz((uint32_t)(row * 128 + lj));
            const size_t gi = (size_t)row * H_ + k0 + lj / 2;
            cp16(sAh + so, Xh + gi);
            cp16(sAl + so, Xl + gi);
            cp16(sBh + so, Wh + gi);
            cp16(sBl + so, Wl + gi);
        }
        CP_COMMIT();
    };

    // Prologue
    load_chunk(0, 0);

    const int lr  = lane & 15;            // row within 16-row ldmatrix tile
    const int lcb = ((lane >> 4) << 3) * 2; // 0 or 16 bytes (k half)

    for (int c = 0; c < 16; c++) {
        const int s = c & 1;
        CP_WAIT0();
        __syncthreads();
        if (c + 1 < 16) load_chunk(c + 1, (c + 1) & 1);

        const uint32_t sAh = sb + OFF_AH2(s), sAl = sb + OFF_AL2(s);
        const uint32_t sBh = sb + OFF_BH2(s), sBl = sb + OFF_BL2(s);

        #pragma unroll
        for (int kk = 0; kk < 4; kk++) {
            const int kbyte = kk * 32 + lcb;

            uint32_t ah[4][4], al[4][4];
            #pragma unroll
            for (int mt = 0; mt < 4; mt++) {
                const uint32_t ro = swz((uint32_t)((warp_m + mt * 16 + lr) * 128 + kbyte));
                ldsm4(ah[mt][0], ah[mt][1], ah[mt][2], ah[mt][3], sAh + ro);
                ldsm4(al[mt][0], al[mt][1], al[mt][2], al[mt][3], sAl + ro);
            }
            uint32_t bh[2][4], bl[2][4];
            #pragma unroll
            for (int g = 0; g < 2; g++) {
                const uint32_t ro = swz((uint32_t)((warp_n + g * 16 + lr) * 128 + kbyte));
                ldsm4(bh[g][0], bh[g][1], bh[g][2], bh[g][3], sBh + ro);
                ldsm4(bl[g][0], bl[g][1], bl[g][2], bl[g][3], sBl + ro);
            }

            #pragma unroll
            for (int mt = 0; mt < 4; mt++) {
                #pragma unroll
                for (int nt = 0; nt < 4; nt++) {
                    const int g  = nt >> 1;        // 16-wide group
                    const int hh = nt & 1;         // 8-wide half within group
                    const uint32_t b0h = bh[g][hh];
                    const uint32_t b1h = bh[g][hh + 2];
                    const uint32_t b0l = bl[g][hh];
                    const uint32_t b1l = bl[g][hh + 2];
                    float* cc = acc[mt][nt];
                    mma16816(cc[0], cc[1], cc[2], cc[3],
                             ah[mt][0], ah[mt][1], ah[mt][2], ah[mt][3], b0h, b1h);
                    mma16816(cc[0], cc[1], cc[2], cc[3],
                             ah[mt][0], ah[mt][1], ah[mt][2], ah[mt][3], b0l, b1l);
                    mma16816(cc[0], cc[1], cc[2], cc[3],
                             al[mt][0], al[mt][1], al[mt][2], al[mt][3], b0h, b1h);
                }
            }
        }
        __syncthreads();
    }

    // ---- Epilogue: add bias, scatter to head-major [b*16+h][s][64] ----
    const int lr4 = lane >> 2;            // 0..7
    const int lc2 = (lane & 3) * 2;       // 0,2,4,6
    #pragma unroll
    for (int mt = 0; mt < 4; mt++) {
        const int mA = m0 + warp_m + mt * 16 + lr4;
        const int mB = mA + 8;
        const int bA = mA >> 10, sA2 = mA & 1023;
        const int bB = mB >> 10, sB2 = mB & 1023;
        #pragma unroll
        for (int nt = 0; nt < 4; nt++) {
            const int n = n0 + warp_n + nt * 8 + lc2;
            const int h = n >> 6, dd = n & 63;
            const float bv0 = bias[n], bv1 = bias[n + 1];
            float* pA = out + (((size_t)(bA * NH_ + h) * S_) + sA2) * D_ + dd;
            float* pB = out + (((size_t)(bB * NH_ + h) * S_) + sB2) * D_ + dd;
            float2 vA = { acc[mt][nt][0] + bv0, acc[mt][nt][1] + bv1 };
            float2 vB = { acc[mt][nt][2] + bv0, acc[mt][nt][3] + bv1 };
            *(float2*)pA = vA;
            *(float2*)pB = vB;
        }
    }
}

// ---------------------------------------------------------------------------
// Flash-style fp32 attention (proven). One thread = one query row.
// ---------------------------------------------------------------------------
#define TKK 64

__global__ __launch_bounds__(128) void attn(
    const float* __restrict__ mask,  // [B][1024]
    float* __restrict__ out)         // [B][S][H]
{
    const int bh  = blockIdx.x;
    const int qt  = blockIdx.y;
    const int b   = bh >> 4;
    const int h   = bh & 15;
    const int tid = threadIdx.x;
    const int q   = qt * 128 + tid;

    __shared__ float ks[TKK][D_];
    __shared__ float vs[TKK][D_];
    __shared__ float ms[TKK];

    const float* qptr = g_q + ((size_t)bh * S_ + q) * D_;
    float4 qreg[16];
    #pragma unroll
    for (int i = 0; i < 16; i++) qreg[i] = *(const float4*)(qptr + i * 4);

    float acc[D_];
    #pragma unroll
    for (int dd = 0; dd < D_; dd++) acc[dd] = 0.f;
    float mmax = -1e30f;
    float lsum = 0.f;
    const float scale = 0.125f;

    const float* kbase = g_k + (size_t)bh * S_ * D_;
    const float* vbase = g_v + (size_t)bh * S_ * D_;
    const float* mbase = mask + (size_t)b * S_;

    for (int k0 = 0; k0 < S_; k0 += TKK) {
        __syncthreads();
        #pragma unroll
        for (int i = 0; i < 8; i++) {
            int f   = tid + i * 128;
            int row = f >> 4;
            int col = (f & 15) * 4;
            *(float4*)&ks[row][col] = *(const float4*)(kbase + (size_t)(k0 + row) * D_ + col);
            *(float4*)&vs[row][col] = *(const float4*)(vbase + (size_t)(k0 + row) * D_ + col);
        }
        if (tid < TKK) ms[tid] = mbase[k0 + tid];
        __syncthreads();

        #pragma unroll 4
        for (int tk = 0; tk < TKK; tk++) {
            const float4* kv = (const float4*)ks[tk];
            float s0 = 0.f, s1 = 0.f, s2 = 0.f, s3 = 0.f;
            #pragma unroll
            for (int i = 0; i < 16; i += 4) {
                float4 k0v = kv[i + 0], k1v = kv[i + 1], k2v = kv[i + 2], k3v = kv[i + 3];
                s0 = fmaf(qreg[i + 0].x, k0v.x, s0); s0 = fmaf(qreg[i + 0].y, k0v.y, s0);
                s0 = fmaf(qreg[i + 0].z, k0v.z, s0); s0 = fmaf(qreg[i + 0].w, k0v.w, s0);
                s1 = fmaf(qreg[i + 1].x, k1v.x, s1); s1 = fmaf(qreg[i + 1].y, k1v.y, s1);
                s1 = fmaf(qreg[i + 1].z, k1v.z, s1); s1 = fmaf(qreg[i + 1].w, k1v.w, s1);
                s2 = fmaf(qreg[i + 2].x, k2v.x, s2); s2 = fmaf(qreg[i + 2].y, k2v.y, s2);
                s2 = fmaf(qreg[i + 2].z, k2v.z, s2); s2 = fmaf(qreg[i + 2].w, k2v.w, s2);
                s3 = fmaf(qreg[i + 3].x, k3v.x, s3); s3 = fmaf(qreg[i + 3].y, k3v.y, s3);
                s3 = fmaf(qreg[i + 3].z, k3v.z, s3); s3 = fmaf(qreg[i + 3].w, k3v.w, s3);
            }
            float s = (s0 + s1) + (s2 + s3);
            s = fmaf(s, scale, ms[tk]);

            if (s > mmax) {
                float corr = __expf(mmax - s);
                lsum *= corr;
                #pragma unroll
                for (int dd = 0; dd < D_; dd++) acc[dd] *= corr;
                mmax = s;
            }
            float p = __expf(s - mmax);
            lsum += p;
            const float4* vv = (const float4*)vs[tk];
            #pragma unroll
            for (int i = 0; i < 16; i++) {
                float4 v4 = vv[i];
                acc[i * 4 + 0] = fmaf(p, v4.x, acc[i * 4 + 0]);
                acc[i * 4 + 1] = fmaf(p, v4.y, acc[i * 4 + 1]);
                acc[i * 4 + 2] = fmaf(p, v4.z, acc[i * 4 + 2]);
                acc[i * 4 + 3] = fmaf(p, v4.w, acc[i * 4 + 3]);
            }
        }
    }

    const float inv = 1.f / lsum;
    float* op = out + ((size_t)(b * S_ + q)) * H_ + h * D_;
    #pragma unroll
    for (int i = 0; i < 16; i++) {
        float4 v;
        v.x = acc[i * 4 + 0] * inv;
        v.y = acc[i * 4 + 1] * inv;
        v.z = acc[i * 4 + 2] * inv;
        v.w = acc[i * 4 + 3] * inv;
        *(float4*)(op + i * 4) = v;
    }
}

// ---------------------------------------------------------------------------
// Launch
// ---------------------------------------------------------------------------
extern "C" void kernel_launch(void* const* d_in, const int* in_sizes, int n_in,
                              void* d_out, int out_size)
{
    const float* act  = (const float*)d_in[0];   // [8,1,1024,1024]
    const float* mask = (const float*)d_in[1];   // [8,1,1,1024]
    const float* qw   = (const float*)d_in[2];
    const float* qb   = (const float*)d_in[3];
    const float* kw   = (const float*)d_in[4];
    const float* kb   = (const float*)d_in[5];
    const float* vw   = (const float*)d_in[6];
    const float* vb   = (const float*)d_in[7];
    float* out = (float*)d_out;

    cudaFuncSetAttribute(qkv_mma, cudaFuncAttributeMaxDynamicSharedMemorySize, GSMEM);

    // 1) fp32 -> bf16 hi/lo split
    convert_split<<<2048, 512>>>(act, qw, kw, vw);

    // 2) mma.sync bf16x3 QKV projection into head-major scratch
    dim3 g1(H_ / 128, M_TOT / 128, 3);   // 8 x 64 x 3
    qkv_mma<<<g1, 256, GSMEM>>>(qb, kb, vb);

    // 3) fp32 flash attention
    dim3 g2(B_ * NH_, S_ / 128);         // 128 x 8
    attn<<<g2, 128>>>(mask, out);
}

// round 5
// speedup vs baseline: 2.9808x; 2.1686x over previous
#include <cuda_runtime.h>
#include <cuda_bf16.h>
#include <math.h>
#include <stdint.h>

// Problem shape: B=8, S=1024, H=1024, heads=16, d=64
#define B_    8
#define S_    1024
#define H_    1024
#define NH_   16
#define D_    64
#define M_TOT (B_ * S_)      // 8192 rows of X

#define XN_ ((size_t)M_TOT * H_)
#define WN_ ((size_t)H_ * H_)

// ---------------------------------------------------------------------------
// Device scratch
// ---------------------------------------------------------------------------
__device__ __nv_bfloat16 g_xh[XN_];                  // X hi
__device__ __nv_bfloat16 g_xl[XN_];                  // X lo
__device__ __nv_bfloat16 g_wh[3 * WN_];              // [q|k|v] W hi
__device__ __nv_bfloat16 g_wl[3 * WN_];              // [q|k|v] W lo

// Head-major projected tensors, bf16 hi/lo.
// Q,K: [bh][s][64]; Q pre-scaled by 0.125. V transposed: [bh][64][s].
__device__ __nv_bfloat16 g_qh[XN_], g_ql[XN_];
__device__ __nv_bfloat16 g_kh[XN_], g_kl[XN_];
__device__ __nv_bfloat16 g_vth[XN_], g_vtl[XN_];

// ---------------------------------------------------------------------------
// Helpers (sm_100 baseline ISA: cp.async / ldmatrix / mma.sync)
// ---------------------------------------------------------------------------
__device__ __forceinline__ uint32_t smem_u32(const void* p) {
    uint32_t a;
    asm("{ .reg .u64 t; cvta.to.shared.u64 t, %1; cvt.u32.u64 %0, t; }"
        : "=r"(a) : "l"(p));
    return a;
}

__device__ __forceinline__ uint32_t swz(uint32_t off) {
    return off ^ ((off >> 3) & 0x70);
}

__device__ __forceinline__ void cp16(uint32_t dst, const void* src) {
    asm volatile("cp.async.cg.shared.global [%0], [%1], 16;"
                 :: "r"(dst), "l"(src) : "memory");
}
#define CP_COMMIT() asm volatile("cp.async.commit_group;" ::: "memory")
#define CP_WAIT0()  asm volatile("cp.async.wait_group 0;" ::: "memory")
#define CP_WAIT1()  asm volatile("cp.async.wait_group 1;" ::: "memory")

__device__ __forceinline__ void ldsm4(uint32_t& r0, uint32_t& r1,
                                      uint32_t& r2, uint32_t& r3, uint32_t a) {
    asm volatile("ldmatrix.sync.aligned.m8n8.x4.shared.b16 {%0,%1,%2,%3}, [%4];"
                 : "=r"(r0), "=r"(r1), "=r"(r2), "=r"(r3) : "r"(a));
}

__device__ __forceinline__ void mma16816(float* c,
                                         const uint32_t* a,
                                         uint32_t b0, uint32_t b1) {
    asm volatile(
        "mma.sync.aligned.m16n8k16.row.col.f32.bf16.bf16.f32 "
        "{%0,%1,%2,%3}, {%4,%5,%6,%7}, {%8,%9}, {%0,%1,%2,%3};"
        : "+f"(c[0]), "+f"(c[1]), "+f"(c[2]), "+f"(c[3])
        : "r"(a[0]), "r"(a[1]), "r"(a[2]), "r"(a[3]), "r"(b0), "r"(b1));
}

__device__ __forceinline__ void split_bf16(float y, __nv_bfloat16& h, __nv_bfloat16& l) {
    h = __float2bfloat16_rn(y);
    l = __float2bfloat16_rn(y - __bfloat162float(h));
}

__device__ __forceinline__ uint32_t pack_bf16x2(__nv_bfloat16 lo, __nv_bfloat16 hi) {
    __nv_bfloat162 t;
    t.x = lo; t.y = hi;
    return *(uint32_t*)&t;
}

// ---------------------------------------------------------------------------
// fp32 -> (bf16 hi, bf16 lo) split of X and the three weight matrices
// ---------------------------------------------------------------------------
__global__ __launch_bounds__(512) void convert_split(
    const float* __restrict__ X,
    const float* __restrict__ qw, const float* __restrict__ kw,
    const float* __restrict__ vw)
{
    size_t total = XN_ + 3 * WN_;
    for (size_t i = (size_t)blockIdx.x * blockDim.x + threadIdx.x;
         i < total; i += (size_t)gridDim.x * blockDim.x) {
        float x;
        __nv_bfloat16 *dh, *dl;
        if (i < XN_) {
            x = X[i]; dh = g_xh + i; dl = g_xl + i;
        } else {
            size_t j = i - XN_;
            size_t z = j / WN_;
            size_t r = j - z * WN_;
            x = (z == 0 ? qw : (z == 1 ? kw : vw))[r];
            dh = g_wh + j; dl = g_wl + j;
        }
        __nv_bfloat16 hi, lo;
        split_bf16(x, hi, lo);
        *dh = hi; *dl = lo;
    }
}

// ---------------------------------------------------------------------------
// bf16x3 QKV GEMM via mma.sync: Y = X @ W^T + b -> bf16 hi/lo head-major.
// CTA 128x128, BK=64, 8 warps (2m x 4n), warp tile 64x32, 2-stage cp.async.
// ---------------------------------------------------------------------------
#define TILE_B   (128 * 128)
#define STG_SZ   (4 * TILE_B)
#define GSMEM    (2 * STG_SZ)

#define OFF_AH2(s) ((s) * STG_SZ)
#define OFF_AL2(s) ((s) * STG_SZ + TILE_B)
#define OFF_BH2(s) ((s) * STG_SZ + 2 * TILE_B)
#define OFF_BL2(s) ((s) * STG_SZ + 3 * TILE_B)

__global__ __launch_bounds__(256, 1) void qkv_mma(
    const float* __restrict__ bq, const float* __restrict__ bk,
    const float* __restrict__ bv)
{
    extern __shared__ char smem[];
    const uint32_t sb = smem_u32(smem);

    const int tid  = threadIdx.x;
    const int wid  = tid >> 5;
    const int lane = tid & 31;
    const int z    = blockIdx.z;
    const int m0   = blockIdx.y * 128;
    const int n0   = blockIdx.x * 128;

    const float* bias = (z == 0) ? bq : (z == 1) ? bk : bv;

    const int warp_m = (wid >> 2) * 64;
    const int warp_n = (wid & 3) * 32;

    const __nv_bfloat16* Xh = g_xh + (size_t)m0 * H_;
    const __nv_bfloat16* Xl = g_xl + (size_t)m0 * H_;
    const __nv_bfloat16* Wh = g_wh + (size_t)z * WN_ + (size_t)n0 * H_;
    const __nv_bfloat16* Wl = g_wl + (size_t)z * WN_ + (size_t)n0 * H_;

    float acc[4][4][4];
    #pragma unroll
    for (int i = 0; i < 4; i++)
        #pragma unroll
        for (int j = 0; j < 4; j++)
            #pragma unroll
            for (int t = 0; t < 4; t++) acc[i][j][t] = 0.f;

    const int lrow0 = tid >> 3;
    const int lj    = (tid & 7) * 16;

    auto load_chunk = [&](int c, int s) {
        const int k0 = c * 64;
        const uint32_t sAh = sb + OFF_AH2(s), sAl = sb + OFF_AL2(s);
        const uint32_t sBh = sb + OFF_BH2(s), sBl = sb + OFF_BL2(s);
        #pragma unroll
        for (int it = 0; it < 4; it++) {
            const int row = lrow0 + it * 32;
            const uint32_t so = swz((uint32_t)(row * 128 + lj));
            const size_t gi = (size_t)row * H_ + k0 + lj / 2;
            cp16(sAh + so, Xh + gi);
            cp16(sAl + so, Xl + gi);
            cp16(sBh + so, Wh + gi);
            cp16(sBl + so, Wl + gi);
        }
        CP_COMMIT();
    };

    load_chunk(0, 0);

    const int lr   = lane & 15;
    const int hi16 = (lane >> 4) * 16;

    for (int c = 0; c < 16; c++) {
        const int s = c & 1;
        CP_WAIT0();
        __syncthreads();
        if (c + 1 < 16) load_chunk(c + 1, (c + 1) & 1);

        const uint32_t sAh = sb + OFF_AH2(s), sAl = sb + OFF_AL2(s);
        const uint32_t sBh = sb + OFF_BH2(s), sBl = sb + OFF_BL2(s);

        #pragma unroll
        for (int kk = 0; kk < 4; kk++) {
            const int kbyte = kk * 32 + hi16;

            uint32_t ah[4][4], al[4][4];
            #pragma unroll
            for (int mt = 0; mt < 4; mt++) {
                const uint32_t ro = swz((uint32_t)((warp_m + mt * 16 + lr) * 128 + kbyte));
                ldsm4(ah[mt][0], ah[mt][1], ah[mt][2], ah[mt][3], sAh + ro);
                ldsm4(al[mt][0], al[mt][1], al[mt][2], al[mt][3], sAl + ro);
            }
            uint32_t bh[2][4], bl[2][4];
            #pragma unroll
            for (int g = 0; g < 2; g++) {
                const uint32_t ro = swz((uint32_t)((warp_n + g * 16 + lr) * 128 + kbyte));
                ldsm4(bh[g][0], bh[g][1], bh[g][2], bh[g][3], sBh + ro);
                ldsm4(bl[g][0], bl[g][1], bl[g][2], bl[g][3], sBl + ro);
            }

            #pragma unroll
            for (int mt = 0; mt < 4; mt++) {
                #pragma unroll
                for (int nt = 0; nt < 4; nt++) {
                    const int g  = nt >> 1;
                    const int hh = nt & 1;
                    mma16816(acc[mt][nt], ah[mt], bh[g][hh], bh[g][hh + 2]);
                    mma16816(acc[mt][nt], ah[mt], bl[g][hh], bl[g][hh + 2]);
                    mma16816(acc[mt][nt], al[mt], bh[g][hh], bh[g][hh + 2]);
                }
            }
        }
        __syncthreads();
    }

    // ---- Epilogue: bias (+0.125 scale for Q), bf16 split, head-major store ----
    const int lr4 = lane >> 2;
    const int lc2 = (lane & 3) * 2;
    const float scale = (z == 0) ? 0.125f : 1.0f;

    __nv_bfloat16* outh = (z == 0) ? g_qh : (z == 1) ? g_kh : g_vth;
    __nv_bfloat16* outl = (z == 0) ? g_ql : (z == 1) ? g_kl : g_vtl;

    #pragma unroll
    for (int mt = 0; mt < 4; mt++) {
        const int mA = m0 + warp_m + mt * 16 + lr4;
        const int mB = mA + 8;
        const int bhA = (mA >> 10) * NH_, sA2 = mA & 1023;
        const int bhB = (mB >> 10) * NH_, sB2 = mB & 1023;
        #pragma unroll
        for (int nt = 0; nt < 4; nt++) {
            const int n  = n0 + warp_n + nt * 8 + lc2;
            const int h  = n >> 6, dd = n & 63;
            const float bv0 = bias[n], bv1 = bias[n + 1];
            float y00 = (acc[mt][nt][0] + bv0) * scale;
            float y01 = (acc[mt][nt][1] + bv1) * scale;
            float y10 = (acc[mt][nt][2] + bv0) * scale;
            float y11 = (acc[mt][nt][3] + bv1) * scale;
            __nv_bfloat16 h00, l00, h01, l01, h10, l10, h11, l11;
            split_bf16(y00, h00, l00); split_bf16(y01, h01, l01);
            split_bf16(y10, h10, l10); split_bf16(y11, h11, l11);
            if (z < 2) {
                const size_t pA = ((size_t)(bhA + h) * S_ + sA2) * D_ + dd;
                const size_t pB = ((size_t)(bhB + h) * S_ + sB2) * D_ + dd;
                *(uint32_t*)(outh + pA) = pack_bf16x2(h00, h01);
                *(uint32_t*)(outl + pA) = pack_bf16x2(l00, l01);
                *(uint32_t*)(outh + pB) = pack_bf16x2(h10, h11);
                *(uint32_t*)(outl + pB) = pack_bf16x2(l10, l11);
            } else {
                // V transposed: [bh][dd][s]
                const size_t rA0 = ((size_t)(bhA + h) * D_ + dd) * S_ + sA2;
                const size_t rB0 = ((size_t)(bhB + h) * D_ + dd) * S_ + sB2;
                outh[rA0] = h00;       outl[rA0] = l00;
                outh[rA0 + S_] = h01;  outl[rA0 + S_] = l01;
                outh[rB0] = h10;       outl[rB0] = l10;
                outh[rB0 + S_] = h11;  outl[rB0 + S_] = l11;
            }
        }
    }
}

// ---------------------------------------------------------------------------
// Tensor-core flash attention. CTA = 128 q-rows, 8 warps x 16 rows.
// Loop over 8 key tiles of 128; S via bf16x3 mma; softmax in registers
// (quad shfl reductions); P hi/lo -> warp-private smem -> PV bf16x3 mma.
// grid: (8 q-tiles, 128 bh) so CTAs sharing K/V are L2-coresident.
// ---------------------------------------------------------------------------
#define AT_STG    65536
#define AT_KH     0
#define AT_KL     16384
#define AT_VH(hf) (32768 + (hf) * 8192)
#define AT_VL(hf) (49152 + (hf) * 8192)
#define AT_PH     131072
#define AT_PL     147456
#define AT_MASK   163840
#define AT_SMEM   167936

__global__ __launch_bounds__(256, 1) void attn_mma(
    const float* __restrict__ mask,  // [B][1024]
    float* __restrict__ out)         // [B][S][H]
{
    extern __shared__ char smem[];
    const uint32_t sb = smem_u32(smem);

    const int tid  = threadIdx.x;
    const int wid  = tid >> 5;
    const int lane = tid & 31;
    const int qt   = blockIdx.x;     // 0..7
    const int bh   = blockIdx.y;     // 0..127
    const int b    = bh >> 4;
    const int h    = bh & 15;
    const int q0   = qt * 128;

    const int lr   = lane & 15;
    const int hi16 = (lane >> 4) * 16;
    const int r1   = lane >> 2;
    const int c01  = (lane & 3) * 2;

    const __nv_bfloat16* Qh = g_qh + ((size_t)bh * S_ + q0) * D_;
    const __nv_bfloat16* Ql = g_ql + ((size_t)bh * S_ + q0) * D_;
    const __nv_bfloat16* Kh = g_kh + (size_t)bh * S_ * D_;
    const __nv_bfloat16* Kl = g_kl + (size_t)bh * S_ * D_;
    const __nv_bfloat16* Vh = g_vth + (size_t)bh * D_ * S_;
    const __nv_bfloat16* Vl = g_vtl + (size_t)bh * D_ * S_;

    // Group 0: Q tile (into P region) + mask
    {
        #pragma unroll
        for (int it = 0; it < 4; it++) {
            const int f = tid + it * 256;
            const int row = f >> 3, j = f & 7;
            const uint32_t so = swz((uint32_t)(row * 128 + j * 16));
            cp16(sb + AT_PH + so, Qh + (size_t)row * D_ + j * 8);
            cp16(sb + AT_PL + so, Ql + (size_t)row * D_ + j * 8);
        }
        cp16(sb + AT_MASK + tid * 16, mask + (size_t)b * S_ + tid * 4);
        CP_COMMIT();
    }

    auto load_kv = [&](int kt, int s) {
        const uint32_t base = sb + s * AT_STG;
        const int k0 = kt * 128;
        #pragma unroll
        for (int it = 0; it < 4; it++) {
            const int f = tid + it * 256;
            const int row = f >> 3, j = f & 7;
            const uint32_t so = swz((uint32_t)(row * 128 + j * 16));
            cp16(base + AT_KH + so, Kh + (size_t)(k0 + row) * D_ + j * 8);
            cp16(base + AT_KL + so, Kl + (size_t)(k0 + row) * D_ + j * 8);
        }
        #pragma unroll
        for (int it = 0; it < 2; it++) {
            const int f = tid + it * 256;
            const int row = f >> 3, j = f & 7;   // row = d (0..63)
            const uint32_t so = swz((uint32_t)(row * 128 + j * 16));
            #pragma unroll
            for (int hf = 0; hf < 2; hf++) {
                const size_t gi = (size_t)row * S_ + k0 + hf * 64 + j * 8;
                cp16(base + AT_VH(hf) + so, Vh + gi);
                cp16(base + AT_VL(hf) + so, Vl + gi);
            }
        }
        CP_COMMIT();
    };

    load_kv(0, 0);   // group 1

    CP_WAIT1();      // group 0 (Q + mask) done
    __syncthreads();

    // Q fragments (resident all kernel)
    uint32_t qfh[4][4], qfl[4][4];
    #pragma unroll
    for (int kk = 0; kk < 4; kk++) {
        const uint32_t ro = swz((uint32_t)((wid * 16 + lr) * 128 + kk * 32 + hi16));
        ldsm4(qfh[kk][0], qfh[kk][1], qfh[kk][2], qfh[kk][3], sb + AT_PH + ro);
        ldsm4(qfl[kk][0], qfl[kk][1], qfl[kk][2], qfl[kk][3], sb + AT_PL + ro);
    }
    __syncthreads();   // P region free for reuse

    float O[8][4];
    #pragma unroll
    for (int i = 0; i < 8; i++)
        #pragma unroll
        for (int t = 0; t < 4; t++) O[i][t] = 0.f;
    float m0 = -1e30f, m1 = -1e30f, l0 = 0.f, l1 = 0.f;

    const float* msk = (const float*)(smem + AT_MASK);

    for (int kt = 0; kt < 8; kt++) {
        CP_WAIT0();
        __syncthreads();
        if (kt < 7) load_kv(kt + 1, (kt + 1) & 1);
        const uint32_t base = sb + (kt & 1) * AT_STG;

        // ---- S = Q K^T (pre-scaled Q) ----
        float S[16][4];
        #pragma unroll
        for (int i = 0; i < 16; i++)
            #pragma unroll
            for (int t = 0; t < 4; t++) S[i][t] = 0.f;

        #pragma unroll
        for (int kk = 0; kk < 4; kk++) {
            const int kbyte = kk * 32 + hi16;
            #pragma unroll
            for (int g = 0; g < 8; g++) {
                uint32_t kh[4], kl[4];
                const uint32_t ro = swz((uint32_t)((g * 16 + lr) * 128 + kbyte));
                ldsm4(kh[0], kh[1], kh[2], kh[3], base + AT_KH + ro);
                ldsm4(kl[0], kl[1], kl[2], kl[3], base + AT_KL + ro);
                #pragma unroll
                for (int hh = 0; hh < 2; hh++) {
                    float* s = S[g * 2 + hh];
                    mma16816(s, qfh[kk], kh[hh], kh[hh + 2]);
                    mma16816(s, qfh[kk], kl[hh], kl[hh + 2]);
                    mma16816(s, qfl[kk], kh[hh], kh[hh + 2]);
                }
            }
        }

        // ---- mask + online softmax ----
        float mx0 = -1e30f, mx1 = -1e30f;
        #pragma unroll
        for (int nt = 0; nt < 16; nt++) {
            const float2 mv = *(const float2*)(msk + kt * 128 + nt * 8 + c01);
            S[nt][0] += mv.x; S[nt][1] += mv.y;
            S[nt][2] += mv.x; S[nt][3] += mv.y;
            mx0 = fmaxf(mx0, fmaxf(S[nt][0], S[nt][1]));
            mx1 = fmaxf(mx1, fmaxf(S[nt][2], S[nt][3]));
        }
        mx0 = fmaxf(mx0, __shfl_xor_sync(0xffffffffu, mx0, 1));
        mx0 = fmaxf(mx0, __shfl_xor_sync(0xffffffffu, mx0, 2));
        mx1 = fmaxf(mx1, __shfl_xor_sync(0xffffffffu, mx1, 1));
        mx1 = fmaxf(mx1, __shfl_xor_sync(0xffffffffu, mx1, 2));

        const float nm0 = fmaxf(m0, mx0);
        const float nm1 = fmaxf(m1, mx1);
        const float f0 = __expf(m0 - nm0);
        const float f1 = __expf(m1 - nm1);
        m0 = nm0; m1 = nm1;
        l0 *= f0; l1 *= f1;
        #pragma unroll
        for (int on = 0; on < 8; on++) {
            O[on][0] *= f0; O[on][1] *= f0;
            O[on][2] *= f1; O[on][3] *= f1;
        }

        float s0 = 0.f, s1 = 0.f;
        #pragma unroll
        for (int nt = 0; nt < 16; nt++) {
            S[nt][0] = __expf(S[nt][0] - m0);
            S[nt][1] = __expf(S[nt][1] - m0);
            S[nt][2] = __expf(S[nt][2] - m1);
            S[nt][3] = __expf(S[nt][3] - m1);
            s0 += S[nt][0] + S[nt][1];
            s1 += S[nt][2] + S[nt][3];
        }
        s0 += __shfl_xor_sync(0xffffffffu, s0, 1);
        s0 += __shfl_xor_sync(0xffffffffu, s0, 2);
        s1 += __shfl_xor_sync(0xffffffffu, s1, 1);
        s1 += __shfl_xor_sync(0xffffffffu, s1, 2);
        l0 += s0; l1 += s1;

        // ---- PV per 64-key half: P hi/lo -> smem (warp-private rows) -> mma
        #pragma unroll
        for (int hf = 0; hf < 2; hf++) {
            #pragma unroll
            for (int ntL = 0; ntL < 8; ntL++) {
                const int nt = hf * 8 + ntL;
                __nv_bfloat16 ph0, pl0, ph1, pl1, ph2, pl2, ph3, pl3;
                split_bf16(S[nt][0], ph0, pl0);
                split_bf16(S[nt][1], ph1, pl1);
                split_bf16(S[nt][2], ph2, pl2);
                split_bf16(S[nt][3], ph3, pl3);
                const uint32_t cb = (uint32_t)(ntL * 16 + (lane & 3) * 4);
                const uint32_t o0 = swz((uint32_t)((wid * 16 + r1) * 128) + cb);
                const uint32_t o1 = swz((uint32_t)((wid * 16 + r1 + 8) * 128) + cb);
                *(uint32_t*)(smem + AT_PH + o0) = pack_bf16x2(ph0, ph1);
                *(uint32_t*)(smem + AT_PL + o0) = pack_bf16x2(pl0, pl1);
                *(uint32_t*)(smem + AT_PH + o1) = pack_bf16x2(ph2, ph3);
                *(uint32_t*)(smem + AT_PL + o1) = pack_bf16x2(pl2, pl3);
            }
            __syncwarp();

            #pragma unroll
            for (int kc = 0; kc < 4; kc++) {
                const int kbyte = kc * 32 + hi16;
                uint32_t pah[4], pal[4];
                const uint32_t ro = swz((uint32_t)((wid * 16 + lr) * 128 + kbyte));
                ldsm4(pah[0], pah[1], pah[2], pah[3], sb + AT_PH + ro);
                ldsm4(pal[0], pal[1], pal[2], pal[3], sb + AT_PL + ro);
                #pragma unroll
                for (int g = 0; g < 4; g++) {
                    uint32_t vh[4], vl[4];
                    const uint32_t rv = swz((uint32_t)((g * 16 + lr) * 128 + kbyte));
                    ldsm4(vh[0], vh[1], vh[2], vh[3], base + AT_VH(hf) + rv);
                    ldsm4(vl[0], vl[1], vl[2], vl[3], base + AT_VL(hf) + rv);
                    #pragma unroll
                    for (int hh = 0; hh < 2; hh++) {
                        float* o = O[g * 2 + hh];
                        mma16816(o, pah, vh[hh], vh[hh + 2]);
                        mma16816(o, pal, vh[hh], vh[hh + 2]);
                        mma16816(o, pah, vl[hh], vl[hh + 2]);
                    }
                }
            }
            __syncwarp();
        }
    }

    // ---- Epilogue: normalize, write out [b][s][h*64+d] ----
    const float inv0 = 1.f / l0;
    const float inv1 = 1.f / l1;
    const int s_row0 = q0 + wid * 16 + r1;
    const int s_row1 = s_row0 + 8;
    #pragma unroll
    for (int on = 0; on < 8; on++) {
        const int d = h * D_ + on * 8 + c01;
        float2 v0 = { O[on][0] * inv0, O[on][1] * inv0 };
        float2 v1 = { O[on][2] * inv1, O[on][3] * inv1 };
        *(float2*)(out + ((size_t)(b * S_ + s_row0)) * H_ + d) = v0;
        *(float2*)(out + ((size_t)(b * S_ + s_row1)) * H_ + d) = v1;
    }
}

// ---------------------------------------------------------------------------
// Launch
// ---------------------------------------------------------------------------
extern "C" void kernel_launch(void* const* d_in, const int* in_sizes, int n_in,
                              void* d_out, int out_size)
{
    const float* act  = (const float*)d_in[0];
    const float* mask = (const float*)d_in[1];
    const float* qw   = (const float*)d_in[2];
    const float* qb   = (const float*)d_in[3];
    const float* kw   = (const float*)d_in[4];
    const float* kb   = (const float*)d_in[5];
    const float* vw   = (const float*)d_in[6];
    const float* vb   = (const float*)d_in[7];
    float* out = (float*)d_out;

    cudaFuncSetAttribute(qkv_mma, cudaFuncAttributeMaxDynamicSharedMemorySize, GSMEM);
    cudaFuncSetAttribute(attn_mma, cudaFuncAttributeMaxDynamicSharedMemorySize, AT_SMEM);

    convert_split<<<2048, 512>>>(act, qw, kw, vw);

    dim3 g1(H_ / 128, M_TOT / 128, 3);
    qkv_mma<<<g1, 256, GSMEM>>>(qb, kb, vb);

    dim3 g2(S_ / 128, B_ * NH_);    // (qt, bh): bh-major => K/V L2 reuse
    attn_mma<<<g2, 256, AT_SMEM>>>(mask, out);
}

// round 6
// speedup vs baseline: 3.0384x; 1.0193x over previous
#include <cuda_runtime.h>
#include <cuda_bf16.h>
#include <math.h>
#include <stdint.h>

// Problem shape: B=8, S=1024, H=1024, heads=16, d=64
#define B_    8
#define S_    1024
#define H_    1024
#define NH_   16
#define D_    64
#define M_TOT (B_ * S_)      // 8192 rows of X

#define XN_ ((size_t)M_TOT * H_)
#define WN_ ((size_t)H_ * H_)

// ---------------------------------------------------------------------------
// Device scratch
// ---------------------------------------------------------------------------
__device__ __nv_bfloat16 g_xh[XN_];                  // X hi
__device__ __nv_bfloat16 g_xl[XN_];                  // X lo
__device__ __nv_bfloat16 g_wh[3 * WN_];              // [q|k|v] W hi
__device__ __nv_bfloat16 g_wl[3 * WN_];              // [q|k|v] W lo

// Head-major projected tensors, bf16 hi/lo.
// Q,K: [bh][s][64]; Q pre-scaled by 0.125. V transposed: [bh][64][s].
__device__ __nv_bfloat16 g_qh[XN_], g_ql[XN_];
__device__ __nv_bfloat16 g_kh[XN_], g_kl[XN_];
__device__ __nv_bfloat16 g_vth[XN_], g_vtl[XN_];

// ---------------------------------------------------------------------------
// Helpers (sm_100 baseline ISA: cp.async / ldmatrix / mma.sync)
// ---------------------------------------------------------------------------
__device__ __forceinline__ uint32_t smem_u32(const void* p) {
    uint32_t a;
    asm("{ .reg .u64 t; cvta.to.shared.u64 t, %1; cvt.u32.u64 %0, t; }"
        : "=r"(a) : "l"(p));
    return a;
}

__device__ __forceinline__ uint32_t swz(uint32_t off) {
    return off ^ ((off >> 3) & 0x70);
}

__device__ __forceinline__ void cp16(uint32_t dst, const void* src) {
    asm volatile("cp.async.cg.shared.global [%0], [%1], 16;"
                 :: "r"(dst), "l"(src) : "memory");
}
#define CP_COMMIT() asm volatile("cp.async.commit_group;" ::: "memory")
#define CP_WAIT0()  asm volatile("cp.async.wait_group 0;" ::: "memory")
#define CP_WAIT1()  asm volatile("cp.async.wait_group 1;" ::: "memory")

__device__ __forceinline__ void ldsm4(uint32_t& r0, uint32_t& r1,
                                      uint32_t& r2, uint32_t& r3, uint32_t a) {
    asm volatile("ldmatrix.sync.aligned.m8n8.x4.shared.b16 {%0,%1,%2,%3}, [%4];"
                 : "=r"(r0), "=r"(r1), "=r"(r2), "=r"(r3) : "r"(a));
}

__device__ __forceinline__ void mma16816(float* c,
                                         const uint32_t* a,
                                         uint32_t b0, uint32_t b1) {
    asm volatile(
        "mma.sync.aligned.m16n8k16.row.col.f32.bf16.bf16.f32 "
        "{%0,%1,%2,%3}, {%4,%5,%6,%7}, {%8,%9}, {%0,%1,%2,%3};"
        : "+f"(c[0]), "+f"(c[1]), "+f"(c[2]), "+f"(c[3])
        : "r"(a[0]), "r"(a[1]), "r"(a[2]), "r"(a[3]), "r"(b0), "r"(b1));
}

__device__ __forceinline__ void split_bf16(float y, __nv_bfloat16& h, __nv_bfloat16& l) {
    h = __float2bfloat16_rn(y);
    l = __float2bfloat16_rn(y - __bfloat162float(h));
}

__device__ __forceinline__ uint32_t pack_bf16x2(__nv_bfloat16 lo, __nv_bfloat16 hi) {
    __nv_bfloat162 t;
    t.x = lo; t.y = hi;
    return *(uint32_t*)&t;
}

// ---------------------------------------------------------------------------
// fp32 -> (bf16 hi, bf16 lo) split of X and the three weight matrices
// ---------------------------------------------------------------------------
__global__ __launch_bounds__(512) void convert_split(
    const float* __restrict__ X,
    const float* __restrict__ qw, const float* __restrict__ kw,
    const float* __restrict__ vw)
{
    size_t total = XN_ + 3 * WN_;
    for (size_t i = (size_t)blockIdx.x * blockDim.x + threadIdx.x;
         i < total; i += (size_t)gridDim.x * blockDim.x) {
        float x;
        __nv_bfloat16 *dh, *dl;
        if (i < XN_) {
            x = X[i]; dh = g_xh + i; dl = g_xl + i;
        } else {
            size_t j = i - XN_;
            size_t z = j / WN_;
            size_t r = j - z * WN_;
            x = (z == 0 ? qw : (z == 1 ? kw : vw))[r];
            dh = g_wh + j; dl = g_wl + j;
        }
        __nv_bfloat16 hi, lo;
        split_bf16(x, hi, lo);
        *dh = hi; *dl = lo;
    }
}

// ---------------------------------------------------------------------------
// bf16x3 QKV GEMM via mma.sync: Y = X @ W^T + b -> bf16 hi/lo head-major.
// CTA 256x128, BK=64, 8 warps (4m x 2n), warp tile 64x64, 2-stage cp.async.
// grid: (8 n-tiles, 32 m-tiles, 3 matrices), 256 threads.
// ---------------------------------------------------------------------------
#define A_TILE_Q  (256 * 128)                 // 32 KB per A array
#define B_TILE_Q  (128 * 128)                 // 16 KB per B array
#define STG_SZ    (2 * A_TILE_Q + 2 * B_TILE_Q)   // 96 KB
#define GSMEM     (2 * STG_SZ)                // 192 KB

#define OFF_AH2(s) ((s) * STG_SZ)
#define OFF_AL2(s) ((s) * STG_SZ + A_TILE_Q)
#define OFF_BH2(s) ((s) * STG_SZ + 2 * A_TILE_Q)
#define OFF_BL2(s) ((s) * STG_SZ + 2 * A_TILE_Q + B_TILE_Q)

__global__ __launch_bounds__(256, 1) void qkv_mma(
    const float* __restrict__ bq, const float* __restrict__ bk,
    const float* __restrict__ bv)
{
    extern __shared__ char smem[];
    const uint32_t sb = smem_u32(smem);

    const int tid  = threadIdx.x;
    const int wid  = tid >> 5;
    const int lane = tid & 31;
    const int z    = blockIdx.z;
    const int m0   = blockIdx.y * 256;
    const int n0   = blockIdx.x * 128;

    const float* bias = (z == 0) ? bq : (z == 1) ? bk : bv;

    const int warp_m = (wid >> 1) * 64;   // 0,64,128,192
    const int warp_n = (wid & 1) * 64;    // 0,64

    const __nv_bfloat16* Xh = g_xh + (size_t)m0 * H_;
    const __nv_bfloat16* Xl = g_xl + (size_t)m0 * H_;
    const __nv_bfloat16* Wh = g_wh + (size_t)z * WN_ + (size_t)n0 * H_;
    const __nv_bfloat16* Wl = g_wl + (size_t)z * WN_ + (size_t)n0 * H_;

    float acc[4][8][4];
    #pragma unroll
    for (int i = 0; i < 4; i++)
        #pragma unroll
        for (int j = 0; j < 8; j++)
            #pragma unroll
            for (int t = 0; t < 4; t++) acc[i][j][t] = 0.f;

    const int lrow0 = tid >> 3;          // 0..31
    const int lj    = (tid & 7) * 16;

    auto load_chunk = [&](int c, int s) {
        const int k0 = c * 64;
        const uint32_t sAh = sb + OFF_AH2(s), sAl = sb + OFF_AL2(s);
        const uint32_t sBh = sb + OFF_BH2(s), sBl = sb + OFF_BL2(s);
        #pragma unroll
        for (int it = 0; it < 8; it++) {          // A: 256 rows
            const int row = lrow0 + it * 32;
            const uint32_t so = swz((uint32_t)(row * 128 + lj));
            const size_t gi = (size_t)row * H_ + k0 + lj / 2;
            cp16(sAh + so, Xh + gi);
            cp16(sAl + so, Xl + gi);
        }
        #pragma unroll
        for (int it = 0; it < 4; it++) {          // B: 128 rows
            const int row = lrow0 + it * 32;
            const uint32_t so = swz((uint32_t)(row * 128 + lj));
            const size_t gi = (size_t)row * H_ + k0 + lj / 2;
            cp16(sBh + so, Wh + gi);
            cp16(sBl + so, Wl + gi);
        }
        CP_COMMIT();
    };

    load_chunk(0, 0);

    const int lr   = lane & 15;
    const int hi16 = (lane >> 4) * 16;

    for (int c = 0; c < 16; c++) {
        const int s = c & 1;
        CP_WAIT0();
        __syncthreads();
        if (c + 1 < 16) load_chunk(c + 1, (c + 1) & 1);

        const uint32_t sAh = sb + OFF_AH2(s), sAl = sb + OFF_AL2(s);
        const uint32_t sBh = sb + OFF_BH2(s), sBl = sb + OFF_BL2(s);

        #pragma unroll
        for (int kk = 0; kk < 4; kk++) {
            const int kbyte = kk * 32 + hi16;

            uint32_t ah[4][4], al[4][4];
            #pragma unroll
            for (int mt = 0; mt < 4; mt++) {
                const uint32_t ro = swz((uint32_t)((warp_m + mt * 16 + lr) * 128 + kbyte));
                ldsm4(ah[mt][0], ah[mt][1], ah[mt][2], ah[mt][3], sAh + ro);
                ldsm4(al[mt][0], al[mt][1], al[mt][2], al[mt][3], sAl + ro);
            }
            #pragma unroll
            for (int g = 0; g < 4; g++) {
                uint32_t bh[4], bl[4];
                const uint32_t ro = swz((uint32_t)((warp_n + g * 16 + lr) * 128 + kbyte));
                ldsm4(bh[0], bh[1], bh[2], bh[3], sBh + ro);
                ldsm4(bl[0], bl[1], bl[2], bl[3], sBl + ro);
                #pragma unroll
                for (int mt = 0; mt < 4; mt++) {
                    #pragma unroll
                    for (int hh = 0; hh < 2; hh++) {
                        float* cc = acc[mt][g * 2 + hh];
                        mma16816(cc, ah[mt], bh[hh], bh[hh + 2]);
                        mma16816(cc, ah[mt], bl[hh], bl[hh + 2]);
                        mma16816(cc, al[mt], bh[hh], bh[hh + 2]);
                    }
                }
            }
        }
        __syncthreads();
    }

    // ---- Epilogue: bias (+0.125 scale for Q), bf16 split, head-major store ----
    const int lr4 = lane >> 2;
    const int lc2 = (lane & 3) * 2;
    const float scale = (z == 0) ? 0.125f : 1.0f;

    __nv_bfloat16* outh = (z == 0) ? g_qh : (z == 1) ? g_kh : g_vth;
    __nv_bfloat16* outl = (z == 0) ? g_ql : (z == 1) ? g_kl : g_vtl;

    #pragma unroll
    for (int mt = 0; mt < 4; mt++) {
        const int mA = m0 + warp_m + mt * 16 + lr4;
        const int mB = mA + 8;
        const int bhA = (mA >> 10) * NH_, sA2 = mA & 1023;
        const int bhB = (mB >> 10) * NH_, sB2 = mB & 1023;
        #pragma unroll
        for (int nt = 0; nt < 8; nt++) {
            const int n  = n0 + warp_n + nt * 8 + lc2;
            const int h  = n >> 6, dd = n & 63;
            const float bv0 = bias[n], bv1 = bias[n + 1];
            float y00 = (acc[mt][nt][0] + bv0) * scale;
            float y01 = (acc[mt][nt][1] + bv1) * scale;
            float y10 = (acc[mt][nt][2] + bv0) * scale;
            float y11 = (acc[mt][nt][3] + bv1) * scale;
            __nv_bfloat16 h00, l00, h01, l01, h10, l10, h11, l11;
            split_bf16(y00, h00, l00); split_bf16(y01, h01, l01);
            split_bf16(y10, h10, l10); split_bf16(y11, h11, l11);
            if (z < 2) {
                const size_t pA = ((size_t)(bhA + h) * S_ + sA2) * D_ + dd;
                const size_t pB = ((size_t)(bhB + h) * S_ + sB2) * D_ + dd;
                *(uint32_t*)(outh + pA) = pack_bf16x2(h00, h01);
                *(uint32_t*)(outl + pA) = pack_bf16x2(l00, l01);
                *(uint32_t*)(outh + pB) = pack_bf16x2(h10, h11);
                *(uint32_t*)(outl + pB) = pack_bf16x2(l10, l11);
            } else {
                // V transposed: [bh][dd][s]
                const size_t rA0 = ((size_t)(bhA + h) * D_ + dd) * S_ + sA2;
                const size_t rB0 = ((size_t)(bhB + h) * D_ + dd) * S_ + sB2;
                outh[rA0] = h00;       outl[rA0] = l00;
                outh[rA0 + S_] = h01;  outl[rA0 + S_] = l01;
                outh[rB0] = h10;       outl[rB0] = l10;
                outh[rB0 + S_] = h11;  outl[rB0 + S_] = l11;
            }
        }
    }
}

// ---------------------------------------------------------------------------
// Tensor-core flash attention. CTA = 128 q-rows, 8 warps x 16 rows.
// S via bf16x3 mma; softmax in registers (quad shfl); P fragments packed
// DIRECTLY from S accumulators (C-layout == A-layout identity) for PV mma.
// ---------------------------------------------------------------------------
#define AT_STG    65536
#define AT_KH     0
#define AT_KL     16384
#define AT_VH(hf) (32768 + (hf) * 8192)
#define AT_VL(hf) (49152 + (hf) * 8192)
#define AT_Q      131072
#define AT_QL     147456
#define AT_MASK   163840
#define AT_SMEM   167936

__global__ __launch_bounds__(256, 1) void attn_mma(
    const float* __restrict__ mask,  // [B][1024]
    float* __restrict__ out)         // [B][S][H]
{
    extern __shared__ char smem[];
    const uint32_t sb = smem_u32(smem);

    const int tid  = threadIdx.x;
    const int wid  = tid >> 5;
    const int lane = tid & 31;
    const int qt   = blockIdx.x;     // 0..7
    const int bh   = blockIdx.y;     // 0..127
    const int b    = bh >> 4;
    const int h    = bh & 15;
    const int q0   = qt * 128;

    const int lr   = lane & 15;
    const int hi16 = (lane >> 4) * 16;
    const int r1   = lane >> 2;
    const int c01  = (lane & 3) * 2;

    const __nv_bfloat16* Qh = g_qh + ((size_t)bh * S_ + q0) * D_;
    const __nv_bfloat16* Ql = g_ql + ((size_t)bh * S_ + q0) * D_;
    const __nv_bfloat16* Kh = g_kh + (size_t)bh * S_ * D_;
    const __nv_bfloat16* Kl = g_kl + (size_t)bh * S_ * D_;
    const __nv_bfloat16* Vh = g_vth + (size_t)bh * D_ * S_;
    const __nv_bfloat16* Vl = g_vtl + (size_t)bh * D_ * S_;

    // Group 0: Q tile + mask
    {
        #pragma unroll
        for (int it = 0; it < 4; it++) {
            const int f = tid + it * 256;
            const int row = f >> 3, j = f & 7;
            const uint32_t so = swz((uint32_t)(row * 128 + j * 16));
            cp16(sb + AT_Q + so, Qh + (size_t)row * D_ + j * 8);
            cp16(sb + AT_QL + so, Ql + (size_t)row * D_ + j * 8);
        }
        cp16(sb + AT_MASK + tid * 16, mask + (size_t)b * S_ + tid * 4);
        CP_COMMIT();
    }

    auto load_kv = [&](int kt, int s) {
        const uint32_t base = sb + s * AT_STG;
        const int k0 = kt * 128;
        #pragma unroll
        for (int it = 0; it < 4; it++) {
            const int f = tid + it * 256;
            const int row = f >> 3, j = f & 7;
            const uint32_t so = swz((uint32_t)(row * 128 + j * 16));
            cp16(base + AT_KH + so, Kh + (size_t)(k0 + row) * D_ + j * 8);
            cp16(base + AT_KL + so, Kl + (size_t)(k0 + row) * D_ + j * 8);
        }
        #pragma unroll
        for (int it = 0; it < 2; it++) {
            const int f = tid + it * 256;
            const int row = f >> 3, j = f & 7;   // row = d (0..63)
            const uint32_t so = swz((uint32_t)(row * 128 + j * 16));
            #pragma unroll
            for (int hf = 0; hf < 2; hf++) {
                const size_t gi = (size_t)row * S_ + k0 + hf * 64 + j * 8;
                cp16(base + AT_VH(hf) + so, Vh + gi);
                cp16(base + AT_VL(hf) + so, Vl + gi);
            }
        }
        CP_COMMIT();
    };

    load_kv(0, 0);   // group 1

    CP_WAIT1();      // group 0 (Q + mask) done
    __syncthreads();

    // Q fragments (resident all kernel)
    uint32_t qfh[4][4], qfl[4][4];
    #pragma unroll
    for (int kk = 0; kk < 4; kk++) {
        const uint32_t ro = swz((uint32_t)((wid * 16 + lr) * 128 + kk * 32 + hi16));
        ldsm4(qfh[kk][0], qfh[kk][1], qfh[kk][2], qfh[kk][3], sb + AT_Q + ro);
        ldsm4(qfl[kk][0], qfl[kk][1], qfl[kk][2], qfl[kk][3], sb + AT_QL + ro);
    }

    float O[8][4];
    #pragma unroll
    for (int i = 0; i < 8; i++)
        #pragma unroll
        for (int t = 0; t < 4; t++) O[i][t] = 0.f;
    float m0 = -1e30f, m1 = -1e30f, l0 = 0.f, l1 = 0.f;

    const float* msk = (const float*)(smem + AT_MASK);

    for (int kt = 0; kt < 8; kt++) {
        CP_WAIT0();
        __syncthreads();
        if (kt < 7) load_kv(kt + 1, (kt + 1) & 1);
        const uint32_t base = sb + (kt & 1) * AT_STG;

        // ---- S = Q K^T (pre-scaled Q) ----
        float S[16][4];
        #pragma unroll
        for (int i = 0; i < 16; i++)
            #pragma unroll
            for (int t = 0; t < 4; t++) S[i][t] = 0.f;

        #pragma unroll
        for (int kk = 0; kk < 4; kk++) {
            const int kbyte = kk * 32 + hi16;
            #pragma unroll
            for (int g = 0; g < 8; g++) {
                uint32_t kh[4], kl[4];
                const uint32_t ro = swz((uint32_t)((g * 16 + lr) * 128 + kbyte));
                ldsm4(kh[0], kh[1], kh[2], kh[3], base + AT_KH + ro);
                ldsm4(kl[0], kl[1], kl[2], kl[3], base + AT_KL + ro);
                #pragma unroll
                for (int hh = 0; hh < 2; hh++) {
                    float* s = S[g * 2 + hh];
                    mma16816(s, qfh[kk], kh[hh], kh[hh + 2]);
                    mma16816(s, qfh[kk], kl[hh], kl[hh + 2]);
                    mma16816(s, qfl[kk], kh[hh], kh[hh + 2]);
                }
            }
        }

        // ---- mask + online softmax ----
        float mx0 = -1e30f, mx1 = -1e30f;
        #pragma unroll
        for (int nt = 0; nt < 16; nt++) {
            const float2 mv = *(const float2*)(msk + kt * 128 + nt * 8 + c01);
            S[nt][0] += mv.x; S[nt][1] += mv.y;
            S[nt][2] += mv.x; S[nt][3] += mv.y;
            mx0 = fmaxf(mx0, fmaxf(S[nt][0], S[nt][1]));
            mx1 = fmaxf(mx1, fmaxf(S[nt][2], S[nt][3]));
        }
        mx0 = fmaxf(mx0, __shfl_xor_sync(0xffffffffu, mx0, 1));
        mx0 = fmaxf(mx0, __shfl_xor_sync(0xffffffffu, mx0, 2));
        mx1 = fmaxf(mx1, __shfl_xor_sync(0xffffffffu, mx1, 1));
        mx1 = fmaxf(mx1, __shfl_xor_sync(0xffffffffu, mx1, 2));

        const float nm0 = fmaxf(m0, mx0);
        const float nm1 = fmaxf(m1, mx1);
        const float f0 = __expf(m0 - nm0);
        const float f1 = __expf(m1 - nm1);
        m0 = nm0; m1 = nm1;
        l0 *= f0; l1 *= f1;
        #pragma unroll
        for (int on = 0; on < 8; on++) {
            O[on][0] *= f0; O[on][1] *= f0;
            O[on][2] *= f1; O[on][3] *= f1;
        }

        float s0 = 0.f, s1 = 0.f;
        #pragma unroll
        for (int nt = 0; nt < 16; nt++) {
            S[nt][0] = __expf(S[nt][0] - m0);
            S[nt][1] = __expf(S[nt][1] - m0);
            S[nt][2] = __expf(S[nt][2] - m1);
            S[nt][3] = __expf(S[nt][3] - m1);
            s0 += S[nt][0] + S[nt][1];
            s1 += S[nt][2] + S[nt][3];
        }
        s0 += __shfl_xor_sync(0xffffffffu, s0, 1);
        s0 += __shfl_xor_sync(0xffffffffu, s0, 2);
        s1 += __shfl_xor_sync(0xffffffffu, s1, 1);
        s1 += __shfl_xor_sync(0xffffffffu, s1, 2);
        l0 += s0; l1 += s1;

        // ---- Pack P fragments directly from S accumulators.
        // C-layout (c0,c1 @ row r1; c2,c3 @ row r1+8) == A-layout
        // (a0 @ row,k-pair; a1 @ row+8; a2,a3 = next 8 keys from tile nt+1).
        uint32_t pH[16][2], pL[16][2];
        #pragma unroll
        for (int nt = 0; nt < 16; nt++) {
            __nv_bfloat16 h0, l0b, h1, l1b, h2, l2b, h3, l3b;
            split_bf16(S[nt][0], h0, l0b);
            split_bf16(S[nt][1], h1, l1b);
            split_bf16(S[nt][2], h2, l2b);
            split_bf16(S[nt][3], h3, l3b);
            pH[nt][0] = pack_bf16x2(h0, h1);
            pH[nt][1] = pack_bf16x2(h2, h3);
            pL[nt][0] = pack_bf16x2(l0b, l1b);
            pL[nt][1] = pack_bf16x2(l2b, l3b);
        }

        // ---- PV: O += P V, keys as MMA-k. 16-key chunks = S tile pairs. ----
        #pragma unroll
        for (int hf = 0; hf < 2; hf++) {
            #pragma unroll
            for (int kc = 0; kc < 4; kc++) {
                const int t0 = hf * 8 + kc * 2;
                uint32_t pah[4] = { pH[t0][0], pH[t0][1], pH[t0 + 1][0], pH[t0 + 1][1] };
                uint32_t pal[4] = { pL[t0][0], pL[t0][1], pL[t0 + 1][0], pL[t0 + 1][1] };
                const int kbyte = kc * 32 + hi16;
                #pragma unroll
                for (int g = 0; g < 4; g++) {
                    uint32_t vh[4], vl[4];
                    const uint32_t rv = swz((uint32_t)((g * 16 + lr) * 128 + kbyte));
                    ldsm4(vh[0], vh[1], vh[2], vh[3], base + AT_VH(hf) + rv);
                    ldsm4(vl[0], vl[1], vl[2], vl[3], base + AT_VL(hf) + rv);
                    #pragma unroll
                    for (int hh = 0; hh < 2; hh++) {
                        float* o = O[g * 2 + hh];
                        mma16816(o, pah, vh[hh], vh[hh + 2]);
                        mma16816(o, pal, vh[hh], vh[hh + 2]);
                        mma16816(o, pah, vl[hh], vl[hh + 2]);
                    }
                }
            }
        }
    }

    // ---- Epilogue: normalize, write out [b][s][h*64+d] ----
    const float inv0 = 1.f / l0;
    const float inv1 = 1.f / l1;
    const int s_row0 = q0 + wid * 16 + r1;
    const int s_row1 = s_row0 + 8;
    #pragma unroll
    for (int on = 0; on < 8; on++) {
        const int d = h * D_ + on * 8 + c01;
        float2 v0 = { O[on][0] * inv0, O[on][1] * inv0 };
        float2 v1 = { O[on][2] * inv1, O[on][3] * inv1 };
        *(float2*)(out + ((size_t)(b * S_ + s_row0)) * H_ + d) = v0;
        *(float2*)(out + ((size_t)(b * S_ + s_row1)) * H_ + d) = v1;
    }
}

// ---------------------------------------------------------------------------
// Launch
// ---------------------------------------------------------------------------
extern "C" void kernel_launch(void* const* d_in, const int* in_sizes, int n_in,
                              void* d_out, int out_size)
{
    const float* act  = (const float*)d_in[0];
    const float* mask = (const float*)d_in[1];
    const float* qw   = (const float*)d_in[2];
    const float* qb   = (const float*)d_in[3];
    const float* kw   = (const float*)d_in[4];
    const float* kb   = (const float*)d_in[5];
    const float* vw   = (const float*)d_in[6];
    const float* vb   = (const float*)d_in[7];
    float* out = (float*)d_out;

    cudaFuncSetAttribute(qkv_mma, cudaFuncAttributeMaxDynamicSharedMemorySize, GSMEM);
    cudaFuncSetAttribute(attn_mma, cudaFuncAttributeMaxDynamicSharedMemorySize, AT_SMEM);

    convert_split<<<2048, 512>>>(act, qw, kw, vw);

    dim3 g1(H_ / 128, M_TOT / 256, 3);   // 8 x 32 x 3
    qkv_mma<<<g1, 256, GSMEM>>>(qb, kb, vb);

    dim3 g2(S_ / 128, B_ * NH_);         // (qt, bh): bh-major => K/V L2 reuse
    attn_mma<<<g2, 256, AT_SMEM>>>(mask, out);
}

// round 7
// speedup vs baseline: 3.1518x; 1.0373x over previous
#include <cuda_runtime.h>
#include <cuda_bf16.h>
#include <math.h>
#include <stdint.h>

// Problem shape: B=8, S=1024, H=1024, heads=16, d=64
#define B_    8
#define S_    1024
#define H_    1024
#define NH_   16
#define D_    64
#define M_TOT (B_ * S_)      // 8192 rows of X

#define XN_ ((size_t)M_TOT * H_)
#define WN_ ((size_t)H_ * H_)

// ---------------------------------------------------------------------------
// Device scratch
// ---------------------------------------------------------------------------
__device__ __nv_bfloat16 g_xh[XN_];                  // X hi
__device__ __nv_bfloat16 g_xl[XN_];                  // X lo
__device__ __nv_bfloat16 g_wh[3 * WN_];              // [q|k|v] W hi
__device__ __nv_bfloat16 g_wl[3 * WN_];              // [q|k|v] W lo

// Head-major projected tensors, bf16 hi/lo.
// Q,K: [bh][s][64]; Q pre-scaled by 0.125. V transposed: [bh][64][s].
__device__ __nv_bfloat16 g_qh[XN_], g_ql[XN_];
__device__ __nv_bfloat16 g_kh[XN_], g_kl[XN_];
__device__ __nv_bfloat16 g_vth[XN_], g_vtl[XN_];

// ---------------------------------------------------------------------------
// Helpers (sm_100 baseline ISA: cp.async / ldmatrix / mma.sync)
// ---------------------------------------------------------------------------
__device__ __forceinline__ uint32_t smem_u32(const void* p) {
    uint32_t a;
    asm("{ .reg .u64 t; cvta.to.shared.u64 t, %1; cvt.u32.u64 %0, t; }"
        : "=r"(a) : "l"(p));
    return a;
}

__device__ __forceinline__ uint32_t swz(uint32_t off) {
    return off ^ ((off >> 3) & 0x70);
}

__device__ __forceinline__ void cp16(uint32_t dst, const void* src) {
    asm volatile("cp.async.cg.shared.global [%0], [%1], 16;"
                 :: "r"(dst), "l"(src) : "memory");
}
#define CP_COMMIT() asm volatile("cp.async.commit_group;" ::: "memory")
#define CP_WAIT0()  asm volatile("cp.async.wait_group 0;" ::: "memory")
#define CP_WAIT1()  asm volatile("cp.async.wait_group 1;" ::: "memory")

__device__ __forceinline__ void ldsm4(uint32_t& r0, uint32_t& r1,
                                      uint32_t& r2, uint32_t& r3, uint32_t a) {
    asm volatile("ldmatrix.sync.aligned.m8n8.x4.shared.b16 {%0,%1,%2,%3}, [%4];"
                 : "=r"(r0), "=r"(r1), "=r"(r2), "=r"(r3) : "r"(a));
}

__device__ __forceinline__ void mma16816(float* c,
                                         const uint32_t* a,
                                         uint32_t b0, uint32_t b1) {
    asm volatile(
        "mma.sync.aligned.m16n8k16.row.col.f32.bf16.bf16.f32 "
        "{%0,%1,%2,%3}, {%4,%5,%6,%7}, {%8,%9}, {%0,%1,%2,%3};"
        : "+f"(c[0]), "+f"(c[1]), "+f"(c[2]), "+f"(c[3])
        : "r"(a[0]), "r"(a[1]), "r"(a[2]), "r"(a[3]), "r"(b0), "r"(b1));
}

__device__ __forceinline__ void split_bf16(float y, __nv_bfloat16& h, __nv_bfloat16& l) {
    h = __float2bfloat16_rn(y);
    l = __float2bfloat16_rn(y - __bfloat162float(h));
}

__device__ __forceinline__ uint32_t pack_bf16x2(__nv_bfloat16 lo, __nv_bfloat16 hi) {
    __nv_bfloat162 t;
    t.x = lo; t.y = hi;
    return *(uint32_t*)&t;
}

// ---------------------------------------------------------------------------
// fp32 -> (bf16 hi, bf16 lo) split of X and the three weight matrices
// ---------------------------------------------------------------------------
__global__ __launch_bounds__(512) void convert_split(
    const float* __restrict__ X,
    const float* __restrict__ qw, const float* __restrict__ kw,
    const float* __restrict__ vw)
{
    size_t total = XN_ + 3 * WN_;
    for (size_t i = (size_t)blockIdx.x * blockDim.x + threadIdx.x;
         i < total; i += (size_t)gridDim.x * blockDim.x) {
        float x;
        __nv_bfloat16 *dh, *dl;
        if (i < XN_) {
            x = X[i]; dh = g_xh + i; dl = g_xl + i;
        } else {
            size_t j = i - XN_;
            size_t z = j / WN_;
            size_t r = j - z * WN_;
            x = (z == 0 ? qw : (z == 1 ? kw : vw))[r];
            dh = g_wh + j; dl = g_wl + j;
        }
        __nv_bfloat16 hi, lo;
        split_bf16(x, hi, lo);
        *dh = hi; *dl = lo;
    }
}

// ---------------------------------------------------------------------------
// bf16x3 QKV GEMM via mma.sync: Y = X @ W^T + b -> bf16 hi/lo head-major.
// CTA 128x128, BK=32 with hi|lo interleaved per 128B row, 3-stage cp.async,
// 8 warps (4m x 2n), warp tile 32x64, 2 CTAs/SM.
// ---------------------------------------------------------------------------
#define A_BYTES_Q  (128 * 128)     // 16 KB (rows: [hi 64B | lo 64B])
#define STG_SZ_Q   (2 * A_BYTES_Q) // A + B = 32 KB
#define GSMEM      (3 * STG_SZ_Q)  // 96 KB

__global__ __launch_bounds__(256, 2) void qkv_mma(
    const float* __restrict__ bq, const float* __restrict__ bk,
    const float* __restrict__ bv)
{
    extern __shared__ char smem[];
    const uint32_t sb = smem_u32(smem);

    const int tid  = threadIdx.x;
    const int wid  = tid >> 5;
    const int lane = tid & 31;
    const int z    = blockIdx.z;
    const int m0   = blockIdx.y * 128;
    const int n0   = blockIdx.x * 128;

    const float* bias = (z == 0) ? bq : (z == 1) ? bk : bv;

    const int warp_m = (wid >> 1) * 32;   // 0,32,64,96
    const int warp_n = (wid & 1) * 64;    // 0,64

    const __nv_bfloat16* Xh = g_xh + (size_t)m0 * H_;
    const __nv_bfloat16* Xl = g_xl + (size_t)m0 * H_;
    const __nv_bfloat16* Wh = g_wh + (size_t)z * WN_ + (size_t)n0 * H_;
    const __nv_bfloat16* Wl = g_wl + (size_t)z * WN_ + (size_t)n0 * H_;

    float acc[2][8][4];
    #pragma unroll
    for (int i = 0; i < 2; i++)
        #pragma unroll
        for (int j = 0; j < 8; j++)
            #pragma unroll
            for (int t = 0; t < 4; t++) acc[i][j][t] = 0.f;

    auto load_chunk = [&](int c, int s) {
        const int k0 = c * 32;
        const uint32_t sA = sb + s * STG_SZ_Q;
        const uint32_t sB = sA + A_BYTES_Q;
        #pragma unroll
        for (int it = 0; it < 4; it++) {
            const int f   = tid + it * 256;       // 0..1023
            const int row = f >> 3, j = f & 7;
            const uint32_t so = swz((uint32_t)(row * 128 + j * 16));
            const size_t gb = (size_t)row * H_ + k0;
            const __nv_bfloat16* srcA = (j < 4) ? Xh + gb + j * 8
                                                : Xl + gb + (j - 4) * 8;
            const __nv_bfloat16* srcB = (j < 4) ? Wh + gb + j * 8
                                                : Wl + gb + (j - 4) * 8;
            cp16(sA + so, srcA);
            cp16(sB + so, srcB);
        }
        CP_COMMIT();
    };

    load_chunk(0, 0);
    load_chunk(1, 1);

    const int lr   = lane & 15;
    const int hi16 = (lane >> 4) * 16;

    for (int c = 0; c < 32; c++) {
        const int s = c - (c / 3) * 3;   // c % 3
        CP_WAIT1();
        __syncthreads();
        if (c + 2 < 32) load_chunk(c + 2, (c + 2) - ((c + 2) / 3) * 3);

        const uint32_t sA = sb + s * STG_SZ_Q;
        const uint32_t sB = sA + A_BYTES_Q;

        #pragma unroll
        for (int kk = 0; kk < 2; kk++) {
            const int kb = kk * 32 + hi16;        // hi window; lo = +64

            uint32_t ah[2][4], al[2][4];
            #pragma unroll
            for (int mt = 0; mt < 2; mt++) {
                const uint32_t rbase = (uint32_t)((warp_m + mt * 16 + lr) * 128);
                ldsm4(ah[mt][0], ah[mt][1], ah[mt][2], ah[mt][3], sA + swz(rbase + kb));
                ldsm4(al[mt][0], al[mt][1], al[mt][2], al[mt][3], sA + swz(rbase + kb + 64));
            }
            #pragma unroll
            for (int g = 0; g < 4; g++) {
                uint32_t bh[4], bl[4];
                const uint32_t rbase = (uint32_t)((warp_n + g * 16 + lr) * 128);
                ldsm4(bh[0], bh[1], bh[2], bh[3], sB + swz(rbase + kb));
                ldsm4(bl[0], bl[1], bl[2], bl[3], sB + swz(rbase + kb + 64));
                #pragma unroll
                for (int mt = 0; mt < 2; mt++) {
                    #pragma unroll
                    for (int hh = 0; hh < 2; hh++) {
                        float* cc = acc[mt][g * 2 + hh];
                        mma16816(cc, ah[mt], bh[hh], bh[hh + 2]);
                        mma16816(cc, ah[mt], bl[hh], bl[hh + 2]);
                        mma16816(cc, al[mt], bh[hh], bh[hh + 2]);
                    }
                }
            }
        }
    }

    // ---- Epilogue: bias (+0.125 scale for Q), bf16 split, head-major store ----
    const int lr4 = lane >> 2;
    const int lc2 = (lane & 3) * 2;
    const float scale = (z == 0) ? 0.125f : 1.0f;

    __nv_bfloat16* outh = (z == 0) ? g_qh : (z == 1) ? g_kh : g_vth;
    __nv_bfloat16* outl = (z == 0) ? g_ql : (z == 1) ? g_kl : g_vtl;

    #pragma unroll
    for (int mt = 0; mt < 2; mt++) {
        const int mA = m0 + warp_m + mt * 16 + lr4;
        const int mB = mA + 8;
        const int bhA = (mA >> 10) * NH_, sA2 = mA & 1023;
        const int bhB = (mB >> 10) * NH_, sB2 = mB & 1023;
        #pragma unroll
        for (int nt = 0; nt < 8; nt++) {
            const int n  = n0 + warp_n + nt * 8 + lc2;
            const int h  = n >> 6, dd = n & 63;
            const float bv0 = bias[n], bv1 = bias[n + 1];
            float y00 = (acc[mt][nt][0] + bv0) * scale;
            float y01 = (acc[mt][nt][1] + bv1) * scale;
            float y10 = (acc[mt][nt][2] + bv0) * scale;
            float y11 = (acc[mt][nt][3] + bv1) * scale;
            __nv_bfloat16 h00, l00, h01, l01, h10, l10, h11, l11;
            split_bf16(y00, h00, l00); split_bf16(y01, h01, l01);
            split_bf16(y10, h10, l10); split_bf16(y11, h11, l11);
            if (z < 2) {
                const size_t pA = ((size_t)(bhA + h) * S_ + sA2) * D_ + dd;
                const size_t pB = ((size_t)(bhB + h) * S_ + sB2) * D_ + dd;
                *(uint32_t*)(outh + pA) = pack_bf16x2(h00, h01);
                *(uint32_t*)(outl + pA) = pack_bf16x2(l00, l01);
                *(uint32_t*)(outh + pB) = pack_bf16x2(h10, h11);
                *(uint32_t*)(outl + pB) = pack_bf16x2(l10, l11);
            } else {
                // V transposed: [bh][dd][s]
                const size_t rA0 = ((size_t)(bhA + h) * D_ + dd) * S_ + sA2;
                const size_t rB0 = ((size_t)(bhB + h) * D_ + dd) * S_ + sB2;
                outh[rA0] = h00;       outl[rA0] = l00;
                outh[rA0 + S_] = h01;  outl[rA0 + S_] = l01;
                outh[rB0] = h10;       outl[rB0] = l10;
                outh[rB0 + S_] = h11;  outl[rB0 + S_] = l11;
            }
        }
    }
}

// ---------------------------------------------------------------------------
// Tensor-core flash attention. CTA = 128 q-rows, 8 warps x 16 rows.
// 64-key tiles (16 iterations), 2-stage cp.async, 2 CTAs/SM.
// S via bf16x3 mma; softmax in registers (quad shfl); P fragments packed
// inline from S accumulators (C-layout == A-layout) for PV mma.
// ---------------------------------------------------------------------------
#define AT_STG_SZ 32768
#define AT_KH     0
#define AT_KL     8192
#define AT_VH     16384
#define AT_VL     24576
#define AT_Q      65536
#define AT_QL     81920
#define AT_MASK   98304
#define AT_SMEM   102400

__global__ __launch_bounds__(256, 2) void attn_mma(
    const float* __restrict__ mask,  // [B][1024]
    float* __restrict__ out)         // [B][S][H]
{
    extern __shared__ char smem[];
    const uint32_t sb = smem_u32(smem);

    const int tid  = threadIdx.x;
    const int wid  = tid >> 5;
    const int lane = tid & 31;
    const int qt   = blockIdx.x;     // 0..7
    const int bh   = blockIdx.y;     // 0..127
    const int b    = bh >> 4;
    const int h    = bh & 15;
    const int q0   = qt * 128;

    const int lr   = lane & 15;
    const int hi16 = (lane >> 4) * 16;
    const int r1   = lane >> 2;
    const int c01  = (lane & 3) * 2;

    const __nv_bfloat16* Qh = g_qh + ((size_t)bh * S_ + q0) * D_;
    const __nv_bfloat16* Ql = g_ql + ((size_t)bh * S_ + q0) * D_;
    const __nv_bfloat16* Kh = g_kh + (size_t)bh * S_ * D_;
    const __nv_bfloat16* Kl = g_kl + (size_t)bh * S_ * D_;
    const __nv_bfloat16* Vh = g_vth + (size_t)bh * D_ * S_;
    const __nv_bfloat16* Vl = g_vtl + (size_t)bh * D_ * S_;

    // Group 0: Q tile + mask
    {
        #pragma unroll
        for (int it = 0; it < 4; it++) {
            const int f = tid + it * 256;
            const int row = f >> 3, j = f & 7;
            const uint32_t so = swz((uint32_t)(row * 128 + j * 16));
            cp16(sb + AT_Q + so, Qh + (size_t)row * D_ + j * 8);
            cp16(sb + AT_QL + so, Ql + (size_t)row * D_ + j * 8);
        }
        cp16(sb + AT_MASK + tid * 16, mask + (size_t)b * S_ + tid * 4);
        CP_COMMIT();
    }

    auto load_kv = [&](int kt, int s) {
        const uint32_t base = sb + s * AT_STG_SZ;
        const int k0 = kt * 64;
        #pragma unroll
        for (int it = 0; it < 2; it++) {          // K: 64 key rows x 128B hi/lo
            const int f = tid + it * 256;         // 0..511
            const int row = f >> 3, j = f & 7;
            const uint32_t so = swz((uint32_t)(row * 128 + j * 16));
            const size_t gi = (size_t)(k0 + row) * D_ + j * 8;
            cp16(base + AT_KH + so, Kh + gi);
            cp16(base + AT_KL + so, Kl + gi);
        }
        #pragma unroll
        for (int it = 0; it < 2; it++) {          // Vt: 64 d rows x 64 keys hi/lo
            const int f = tid + it * 256;
            const int row = f >> 3, j = f & 7;    // row = d
            const uint32_t so = swz((uint32_t)(row * 128 + j * 16));
            const size_t gi = (size_t)row * S_ + k0 + j * 8;
            cp16(base + AT_VH + so, Vh + gi);
            cp16(base + AT_VL + so, Vl + gi);
        }
        CP_COMMIT();
    };

    load_kv(0, 0);   // group 1

    CP_WAIT1();      // group 0 (Q + mask) done
    __syncthreads();

    // Q fragments (resident all kernel)
    uint32_t qfh[4][4], qfl[4][4];
    #pragma unroll
    for (int kk = 0; kk < 4; kk++) {
        const uint32_t ro = swz((uint32_t)((wid * 16 + lr) * 128 + kk * 32 + hi16));
        ldsm4(qfh[kk][0], qfh[kk][1], qfh[kk][2], qfh[kk][3], sb + AT_Q + ro);
        ldsm4(qfl[kk][0], qfl[kk][1], qfl[kk][2], qfl[kk][3], sb + AT_QL + ro);
    }

    float O[8][4];
    #pragma unroll
    for (int i = 0; i < 8; i++)
        #pragma unroll
        for (int t = 0; t < 4; t++) O[i][t] = 0.f;
    float m0 = -1e30f, m1 = -1e30f, l0 = 0.f, l1 = 0.f;

    const float* msk = (const float*)(smem + AT_MASK);

    for (int kt = 0; kt < 16; kt++) {
        CP_WAIT0();
        __syncthreads();
        if (kt < 15) load_kv(kt + 1, (kt + 1) & 1);
        const uint32_t base = sb + (kt & 1) * AT_STG_SZ;

        // ---- S = Q K^T (pre-scaled Q), 64 keys ----
        float S[8][4];
        #pragma unroll
        for (int i = 0; i < 8; i++)
            #pragma unroll
            for (int t = 0; t < 4; t++) S[i][t] = 0.f;

        #pragma unroll
        for (int kk = 0; kk < 4; kk++) {
            const int kbyte = kk * 32 + hi16;
            #pragma unroll
            for (int g = 0; g < 4; g++) {
                uint32_t kh[4], kl[4];
                const uint32_t ro = swz((uint32_t)((g * 16 + lr) * 128 + kbyte));
                ldsm4(kh[0], kh[1], kh[2], kh[3], base + AT_KH + ro);
                ldsm4(kl[0], kl[1], kl[2], kl[3], base + AT_KL + ro);
                #pragma unroll
                for (int hh = 0; hh < 2; hh++) {
                    float* s = S[g * 2 + hh];
                    mma16816(s, qfh[kk], kh[hh], kh[hh + 2]);
                    mma16816(s, qfh[kk], kl[hh], kl[hh + 2]);
                    mma16816(s, qfl[kk], kh[hh], kh[hh + 2]);
                }
            }
        }

        // ---- mask + online softmax ----
        float mx0 = -1e30f, mx1 = -1e30f;
        #pragma unroll
        for (int nt = 0; nt < 8; nt++) {
            const float2 mv = *(const float2*)(msk + kt * 64 + nt * 8 + c01);
            S[nt][0] += mv.x; S[nt][1] += mv.y;
            S[nt][2] += mv.x; S[nt][3] += mv.y;
            mx0 = fmaxf(mx0, fmaxf(S[nt][0], S[nt][1]));
            mx1 = fmaxf(mx1, fmaxf(S[nt][2], S[nt][3]));
        }
        mx0 = fmaxf(mx0, __shfl_xor_sync(0xffffffffu, mx0, 1));
        mx0 = fmaxf(mx0, __shfl_xor_sync(0xffffffffu, mx0, 2));
        mx1 = fmaxf(mx1, __shfl_xor_sync(0xffffffffu, mx1, 1));
        mx1 = fmaxf(mx1, __shfl_xor_sync(0xffffffffu, mx1, 2));

        const float nm0 = fmaxf(m0, mx0);
        const float nm1 = fmaxf(m1, mx1);
        const float f0 = __expf(m0 - nm0);
        const float f1 = __expf(m1 - nm1);
        m0 = nm0; m1 = nm1;
        l0 *= f0; l1 *= f1;
        #pragma unroll
        for (int on = 0; on < 8; on++) {
            O[on][0] *= f0; O[on][1] *= f0;
            O[on][2] *= f1; O[on][3] *= f1;
        }

        float s0 = 0.f, s1 = 0.f;
        #pragma unroll
        for (int nt = 0; nt < 8; nt++) {
            S[nt][0] = __expf(S[nt][0] - m0);
            S[nt][1] = __expf(S[nt][1] - m0);
            S[nt][2] = __expf(S[nt][2] - m1);
            S[nt][3] = __expf(S[nt][3] - m1);
            s0 += S[nt][0] + S[nt][1];
            s1 += S[nt][2] + S[nt][3];
        }
        s0 += __shfl_xor_sync(0xffffffffu, s0, 1);
        s0 += __shfl_xor_sync(0xffffffffu, s0, 2);
        s1 += __shfl_xor_sync(0xffffffffu, s1, 1);
        s1 += __shfl_xor_sync(0xffffffffu, s1, 2);
        l0 += s0; l1 += s1;

        // ---- PV: pack P fragments inline from S (C-layout == A-layout) ----
        #pragma unroll
        for (int kc = 0; kc < 4; kc++) {
            const int t0 = kc * 2;
            uint32_t pah[4], pal[4];
            {
                __nv_bfloat16 ph[8], pl[8];
                split_bf16(S[t0][0], ph[0], pl[0]);
                split_bf16(S[t0][1], ph[1], pl[1]);
                split_bf16(S[t0][2], ph[2], pl[2]);
                split_bf16(S[t0][3], ph[3], pl[3]);
                split_bf16(S[t0 + 1][0], ph[4], pl[4]);
                split_bf16(S[t0 + 1][1], ph[5], pl[5]);
                split_bf16(S[t0 + 1][2], ph[6], pl[6]);
                split_bf16(S[t0 + 1][3], ph[7], pl[7]);
                pah[0] = pack_bf16x2(ph[0], ph[1]);
                pah[1] = pack_bf16x2(ph[2], ph[3]);
                pah[2] = pack_bf16x2(ph[4], ph[5]);
                pah[3] = pack_bf16x2(ph[6], ph[7]);
                pal[0] = pack_bf16x2(pl[0], pl[1]);
                pal[1] = pack_bf16x2(pl[2], pl[3]);
                pal[2] = pack_bf16x2(pl[4], pl[5]);
                pal[3] = pack_bf16x2(pl[6], pl[7]);
            }
            const int kbyte = kc * 32 + hi16;
            #pragma unroll
            for (int g = 0; g < 4; g++) {
                uint32_t vh[4], vl[4];
                const uint32_t rv = swz((uint32_t)((g * 16 + lr) * 128 + kbyte));
                ldsm4(vh[0], vh[1], vh[2], vh[3], base + AT_VH + rv);
                ldsm4(vl[0], vl[1], vl[2], vl[3], base + AT_VL + rv);
                #pragma unroll
                for (int hh = 0; hh < 2; hh++) {
                    float* o = O[g * 2 + hh];
                    mma16816(o, pah, vh[hh], vh[hh + 2]);
                    mma16816(o, pal, vh[hh], vh[hh + 2]);
                    mma16816(o, pah, vl[hh], vl[hh + 2]);
                }
            }
        }
    }

    // ---- Epilogue: normalize, write out [b][s][h*64+d] ----
    const float inv0 = 1.f / l0;
    const float inv1 = 1.f / l1;
    const int s_row0 = q0 + wid * 16 + r1;
    const int s_row1 = s_row0 + 8;
    #pragma unroll
    for (int on = 0; on < 8; on++) {
        const int d = h * D_ + on * 8 + c01;
        float2 v0 = { O[on][0] * inv0, O[on][1] * inv0 };
        float2 v1 = { O[on][2] * inv1, O[on][3] * inv1 };
        *(float2*)(out + ((size_t)(b * S_ + s_row0)) * H_ + d) = v0;
        *(float2*)(out + ((size_t)(b * S_ + s_row1)) * H_ + d) = v1;
    }
}

// ---------------------------------------------------------------------------
// Launch
// ---------------------------------------------------------------------------
extern "C" void kernel_launch(void* const* d_in, const int* in_sizes, int n_in,
                              void* d_out, int out_size)
{
    const float* act  = (const float*)d_in[0];
    const float* mask = (const float*)d_in[1];
    const float* qw   = (const float*)d_in[2];
    const float* qb   = (const float*)d_in[3];
    const float* kw   = (const float*)d_in[4];
    const float* kb   = (const float*)d_in[5];
    const float* vw   = (const float*)d_in[6];
    const float* vb   = (const float*)d_in[7];
    float* out = (float*)d_out;

    cudaFuncSetAttribute(qkv_mma, cudaFuncAttributeMaxDynamicSharedMemorySize, GSMEM);
    cudaFuncSetAttribute(attn_mma, cudaFuncAttributeMaxDynamicSharedMemorySize, AT_SMEM);

    convert_split<<<2048, 512>>>(act, qw, kw, vw);

    dim3 g1(H_ / 128, M_TOT / 128, 3);   // 8 x 64 x 3
    qkv_mma<<<g1, 256, GSMEM>>>(qb, kb, vb);

    dim3 g2(S_ / 128, B_ * NH_);         // (qt, bh): bh-major => K/V L2 reuse
    attn_mma<<<g2, 256, AT_SMEM>>>(mask, out);
}